// round 11
// baseline (speedup 1.0000x reference)
#include <cuda_runtime.h>
#include <cuda_bf16.h>
#include <math.h>
#include <stdint.h>

#define C_IN   256
#define C_B    64
#define K_TAP  27
#define N_MAX  200000
#define BN_EPS 1e-3f

// ---------------- scratch (device globals; no allocation) ----------------
__device__ float g_h1[(size_t)N_MAX * C_B];   // conv1x1a raw
__device__ float g_h2[(size_t)N_MAX * C_B];   // octree conv raw
__device__ float g_h3[(size_t)N_MAX * C_IN];  // conv1x1b raw

__device__ __nv_bfloat16 g_h1h[(size_t)N_MAX * C_B];  // act1 hi
__device__ __nv_bfloat16 g_h1l[(size_t)N_MAX * C_B];  // act1 lo
__device__ __nv_bfloat16 g_w3h[K_TAP * C_B * C_B];    // w3 [k][c][d] hi
__device__ __nv_bfloat16 g_w3l[K_TAP * C_B * C_B];    // lo

__device__ float g_sum1[C_B],  g_sq1[C_B],  g_a1[C_B],  g_c1[C_B];
__device__ float g_sum2[C_B],  g_sq2[C_B],  g_a2[C_B],  g_c2[C_B];
__device__ float g_sum3[C_IN], g_sq3[C_IN], g_a3[C_IN], g_c3[C_IN];

__device__ __forceinline__ float gelu_exact(float x) {
    return 0.5f * x * (1.0f + erff(x * 0.70710678118654752440f));
}

// ---------------- mma/ldsm/cp.async helpers ----------------
__device__ __forceinline__ uint32_t smem_u32(const void* p) {
    uint32_t a;
    asm("{ .reg .u64 t; cvta.to.shared.u64 t, %1; cvt.u32.u64 %0, t; }"
        : "=r"(a) : "l"(p));
    return a;
}
__device__ __forceinline__ void ldsm_x4(uint32_t* r, uint32_t addr) {
    asm volatile("ldmatrix.sync.aligned.m8n8.x4.shared.b16 {%0,%1,%2,%3}, [%4];"
                 : "=r"(r[0]), "=r"(r[1]), "=r"(r[2]), "=r"(r[3]) : "r"(addr));
}
__device__ __forceinline__ void ldsm_x4_t(uint32_t* r, uint32_t addr) {
    asm volatile("ldmatrix.sync.aligned.m8n8.x4.trans.shared.b16 {%0,%1,%2,%3}, [%4];"
                 : "=r"(r[0]), "=r"(r[1]), "=r"(r[2]), "=r"(r[3]) : "r"(addr));
}
__device__ __forceinline__ void mma_bf16(float* d, const uint32_t* a, const uint32_t* b) {
    asm volatile(
        "mma.sync.aligned.m16n8k16.row.col.f32.bf16.bf16.f32 "
        "{%0,%1,%2,%3}, {%4,%5,%6,%7}, {%8,%9}, {%0,%1,%2,%3};"
        : "+f"(d[0]), "+f"(d[1]), "+f"(d[2]), "+f"(d[3])
        : "r"(a[0]), "r"(a[1]), "r"(a[2]), "r"(a[3]), "r"(b[0]), "r"(b[1]));
}
__device__ __forceinline__ void cp16(uint32_t dst, const void* src) {
    asm volatile("cp.async.cg.shared.global [%0], [%1], 16;" :: "r"(dst), "l"(src));
}
__device__ __forceinline__ void cp_commit() {
    asm volatile("cp.async.commit_group;" ::: "memory");
}

__device__ __forceinline__ uint32_t bf2pack(__nv_bfloat16 a, __nv_bfloat16 b) {
    unsigned short ua = *(unsigned short*)&a, ub = *(unsigned short*)&b;
    return (uint32_t)ua | ((uint32_t)ub << 16);
}
__device__ __forceinline__ void split4(float4 v, uint2* hi, uint2* lo) {
    __nv_bfloat16 h0 = __float2bfloat16(v.x), h1 = __float2bfloat16(v.y);
    __nv_bfloat16 h2 = __float2bfloat16(v.z), h3 = __float2bfloat16(v.w);
    __nv_bfloat16 l0 = __float2bfloat16(v.x - __bfloat162float(h0));
    __nv_bfloat16 l1 = __float2bfloat16(v.y - __bfloat162float(h1));
    __nv_bfloat16 l2 = __float2bfloat16(v.z - __bfloat162float(h2));
    __nv_bfloat16 l3 = __float2bfloat16(v.w - __bfloat162float(h3));
    hi->x = bf2pack(h0, h1); hi->y = bf2pack(h2, h3);
    lo->x = bf2pack(l0, l1); lo->y = bf2pack(l2, l3);
}

// epilogue stats: NTILES column-tiles of 8 cols (pairs), reduce over row-lanes,
// atomically accumulate per-column sum/sumsq.
template<int NTILES>
__device__ __forceinline__ void epilogue_stats(const float acc[][NTILES][4],
                                               int row0_w, int n, int colbase,
                                               int lane,
                                               float* __restrict__ sums,
                                               float* __restrict__ sqs) {
    float cs[NTILES * 2], cq[NTILES * 2];
    #pragma unroll
    for (int i = 0; i < NTILES * 2; i++) { cs[i] = 0.f; cq[i] = 0.f; }
    #pragma unroll
    for (int mt = 0; mt < 2; mt++) {
        int r0 = row0_w + mt * 16 + (lane >> 2);
        bool v0 = r0 < n, v1 = (r0 + 8) < n;
        #pragma unroll
        for (int nt = 0; nt < NTILES; nt++) {
            #pragma unroll
            for (int j = 0; j < 2; j++) {
                float a0 = acc[mt][nt][j], a1 = acc[mt][nt][2 + j];
                if (v0) { cs[nt * 2 + j] += a0; cq[nt * 2 + j] += a0 * a0; }
                if (v1) { cs[nt * 2 + j] += a1; cq[nt * 2 + j] += a1 * a1; }
            }
        }
    }
    #pragma unroll
    for (int m = 4; m <= 16; m <<= 1) {
        #pragma unroll
        for (int i = 0; i < NTILES * 2; i++) {
            cs[i] += __shfl_xor_sync(0xffffffffu, cs[i], m);
            cq[i] += __shfl_xor_sync(0xffffffffu, cq[i], m);
        }
    }
    if ((lane >> 2) == 0) {
        #pragma unroll
        for (int i = 0; i < NTILES * 2; i++) {
            int col = colbase + (i >> 1) * 8 + (lane & 3) * 2 + (i & 1);
            atomicAdd(&sums[col], cs[i]);
            atomicAdd(&sqs[col],  cq[i]);
        }
    }
}

// ---------------- stats reset ----------------
__global__ void zero_stats_kernel() {
    int t = threadIdx.x;
    if (t < C_B)  { g_sum1[t] = 0.f; g_sq1[t] = 0.f; g_sum2[t] = 0.f; g_sq2[t] = 0.f; }
    if (t < C_IN) { g_sum3[t] = 0.f; g_sq3[t] = 0.f; }
}

// ---------------- BN finalize ----------------
__device__ __forceinline__ void bnfin_body(const float* sums, const float* sqs,
                                           const float* __restrict__ g,
                                           const float* __restrict__ b,
                                           float* a, float* c, float inv_n) {
    int t = threadIdx.x;
    float m = sums[t] * inv_n;
    float v = sqs[t] * inv_n - m * m;
    if (v < 0.f) v = 0.f;
    float s = g[t] * rsqrtf(v + BN_EPS);
    a[t] = s;
    c[t] = b[t] - m * s;
}
__global__ void bnfin1_kernel(const float* __restrict__ g, const float* __restrict__ b, float inv_n)
{ bnfin_body(g_sum1, g_sq1, g, b, g_a1, g_c1, inv_n); }
__global__ void bnfin2_kernel(const float* __restrict__ g, const float* __restrict__ b, float inv_n)
{ bnfin_body(g_sum2, g_sq2, g, b, g_a2, g_c2, inv_n); }
__global__ void bnfin3_kernel(const float* __restrict__ g, const float* __restrict__ b, float inv_n)
{ bnfin_body(g_sum3, g_sq3, g, b, g_a3, g_c3, inv_n); }

// ---------------- act1: BN+GELU, write bf16 hi/lo split ----------------
__global__ void act1_split_kernel(long long total) {
    long long i = ((long long)blockIdx.x * blockDim.x + threadIdx.x) * 4;
    if (i >= total) return;
    float4 v = *(const float4*)&g_h1[i];
    int c = (int)(i & (C_B - 1));
    v.x = gelu_exact(fmaf(g_a1[c],     v.x, g_c1[c]));
    v.y = gelu_exact(fmaf(g_a1[c + 1], v.y, g_c1[c + 1]));
    v.z = gelu_exact(fmaf(g_a1[c + 2], v.z, g_c1[c + 2]));
    v.w = gelu_exact(fmaf(g_a1[c + 3], v.w, g_c1[c + 3]));
    uint2 hi, lo; split4(v, &hi, &lo);
    *(uint2*)((unsigned short*)g_h1h + i) = hi;
    *(uint2*)((unsigned short*)g_h1l + i) = lo;
}

// ---------------- w3 split (keep [k][c][d] layout) ----------------
__global__ void w3_split_kernel(const float* __restrict__ w3) {
    int i = blockIdx.x * blockDim.x + threadIdx.x;
    if (i >= K_TAP * C_B * C_B) return;
    float v = w3[i];
    __nv_bfloat16 h = __float2bfloat16(v);
    __nv_bfloat16 l = __float2bfloat16(v - __bfloat162float(h));
    g_w3h[i] = h;
    g_w3l[i] = l;
}

// ============== GEMM1 via mma.sync: h1 = data[N,256] @ w1[256,64] ==============
#define G1_AH 0
#define G1_AL 18432
#define G1_BH 36864
#define G1_BL 46080
#define G1_SMEM 55296

__global__ void __launch_bounds__(256) gemm1_mma_kernel(const float* __restrict__ data,
                                                        const float* __restrict__ w1, int n) {
    extern __shared__ char smem[];
    const uint32_t sb = smem_u32(smem);
    const int tid = threadIdx.x;
    const int wid = tid >> 5, lane = tid & 31;
    const int wr = wid & 3, wc = wid >> 2;
    const int row0 = blockIdx.x * 128;

    float acc[2][4][4] = {};
    const uint32_t aOff = (uint32_t)((wr * 32 + (lane & 15)) * 144 + (lane >> 4) * 16);
    const uint32_t bOff = (uint32_t)((lane & 15) * 144 + (wc * 32 + (lane >> 4) * 8) * 2);

    for (int kb = 0; kb < C_IN; kb += 64) {
        #pragma unroll
        for (int j = 0; j < 8; j++) {
            int s = tid + 256 * j;
            int r = s >> 4, f4 = s & 15;
            int rr = row0 + r; if (rr >= n) rr = n - 1;
            float4 v = *(const float4*)(data + (size_t)rr * C_IN + kb + f4 * 4);
            uint2 hi, lo; split4(v, &hi, &lo);
            *(uint2*)(smem + G1_AH + r * 144 + f4 * 8) = hi;
            *(uint2*)(smem + G1_AL + r * 144 + f4 * 8) = lo;
        }
        #pragma unroll
        for (int j = 0; j < 4; j++) {
            int s = tid + 256 * j;
            int r = s >> 4, f4 = s & 15;
            float4 v = *(const float4*)(w1 + (size_t)(kb + r) * C_B + f4 * 4);
            uint2 hi, lo; split4(v, &hi, &lo);
            *(uint2*)(smem + G1_BH + r * 144 + f4 * 8) = hi;
            *(uint2*)(smem + G1_BL + r * 144 + f4 * 8) = lo;
        }
        __syncthreads();

        #pragma unroll
        for (int ks = 0; ks < 4; ks++) {
            uint32_t ah[2][4], al[2][4], bh[2][4], bl[2][4];
            #pragma unroll
            for (int mt = 0; mt < 2; mt++) {
                uint32_t ad = sb + G1_AH + aOff + (uint32_t)(mt * 16 * 144 + ks * 32);
                ldsm_x4(ah[mt], ad);
                ldsm_x4(al[mt], ad + (G1_AL - G1_AH));
            }
            #pragma unroll
            for (int nt2 = 0; nt2 < 2; nt2++) {
                uint32_t bd = sb + G1_BH + bOff + (uint32_t)(ks * 16 * 144 + nt2 * 32);
                ldsm_x4_t(bh[nt2], bd);
                ldsm_x4_t(bl[nt2], bd + (G1_BL - G1_BH));
            }
            #pragma unroll
            for (int mt = 0; mt < 2; mt++) {
                #pragma unroll
                for (int nt = 0; nt < 4; nt++) {
                    const uint32_t* ph = &bh[nt >> 1][(nt & 1) * 2];
                    const uint32_t* pl = &bl[nt >> 1][(nt & 1) * 2];
                    mma_bf16(acc[mt][nt], ah[mt], ph);
                    mma_bf16(acc[mt][nt], ah[mt], pl);
                    mma_bf16(acc[mt][nt], al[mt], ph);
                }
            }
        }
        __syncthreads();
    }

    #pragma unroll
    for (int mt = 0; mt < 2; mt++) {
        int r0 = row0 + wr * 32 + mt * 16 + (lane >> 2);
        #pragma unroll
        for (int nt = 0; nt < 4; nt++) {
            int col = wc * 32 + nt * 8 + (lane & 3) * 2;
            if (r0 < n)
                *(float2*)&g_h1[(size_t)r0 * C_B + col] =
                    make_float2(acc[mt][nt][0], acc[mt][nt][1]);
            if (r0 + 8 < n)
                *(float2*)&g_h1[(size_t)(r0 + 8) * C_B + col] =
                    make_float2(acc[mt][nt][2], acc[mt][nt][3]);
        }
    }
    epilogue_stats<4>(acc, row0 + wr * 32, n, wc * 32, lane, g_sum1, g_sq1);
}

// ============== octree conv via mma.sync + cp.async double buffering ==============
#define OB_AH 0
#define OB_AL 18432
#define OB_WH 36864
#define OB_WL 46080
#define OB_SZ 55296
#define OFF_IDX 0
#define OFF_BUF 13824
#define OCT_SMEM (OFF_BUF + 2 * OB_SZ)   // 124416

__device__ __forceinline__ void issue_tap(uint32_t sb, int buf, int k,
                                          const int* sIdx, int tid) {
    const uint32_t base = sb + OFF_BUF + buf * OB_SZ;
    const int* idx = sIdx + (k << 7);
    #pragma unroll
    for (int j = 0; j < 4; j++) {
        int cid = tid + 256 * j;              // 0..1023
        int r = cid >> 3, q = cid & 7;
        int gr = idx[r];
        uint32_t d = base + (uint32_t)(r * 144 + q * 16);
        cp16(d + OB_AH, g_h1h + (size_t)gr * C_B + q * 8);
        cp16(d + OB_AL, g_h1l + (size_t)gr * C_B + q * 8);
    }
    #pragma unroll
    for (int j = 0; j < 2; j++) {
        int cid = tid + 256 * j;              // 0..511
        int r = cid >> 3, q = cid & 7;
        uint32_t d = base + (uint32_t)(r * 144 + q * 16);
        cp16(d + OB_WH, g_w3h + (size_t)k * 4096 + cid * 8);
        cp16(d + OB_WL, g_w3l + (size_t)k * 4096 + cid * 8);
    }
}

__global__ void __launch_bounds__(256) octconv_mma_kernel(const int* __restrict__ neigh,
                                                          int n) {
    extern __shared__ char smem[];
    const uint32_t sb = smem_u32(smem);
    const int tid = threadIdx.x;
    const int wid = tid >> 5, lane = tid & 31;
    const int wr = wid & 3, wc = wid >> 2;
    const int row0 = blockIdx.x * 128;

    int* sIdx = (int*)(smem + OFF_IDX);
    for (int i = tid; i < K_TAP * 128; i += 256) {
        int r = i / K_TAP, k = i - r * K_TAP;
        int nr = row0 + r;
        sIdx[k * 128 + r] = (nr < n) ? neigh[(size_t)nr * K_TAP + k] : 0;
    }
    __syncthreads();

    issue_tap(sb, 0, 0, sIdx, tid);
    cp_commit();

    float acc[2][4][4] = {};
    const uint32_t aOff = (uint32_t)((wr * 32 + (lane & 15)) * 144 + (lane >> 4) * 16);
    const uint32_t bOff = (uint32_t)((lane & 15) * 144 + (wc * 32 + (lane >> 4) * 8) * 2);

    for (int k = 0; k < K_TAP; k++) {
        const int b = k & 1;
        if (k + 1 < K_TAP) {
            issue_tap(sb, b ^ 1, k + 1, sIdx, tid);
            cp_commit();
            asm volatile("cp.async.wait_group 1;" ::: "memory");
        } else {
            asm volatile("cp.async.wait_group 0;" ::: "memory");
        }
        __syncthreads();

        const uint32_t base = sb + OFF_BUF + b * OB_SZ;
        #pragma unroll
        for (int ks = 0; ks < 4; ks++) {
            uint32_t ah[2][4], al[2][4], bh[2][4], bl[2][4];
            #pragma unroll
            for (int mt = 0; mt < 2; mt++) {
                uint32_t ad = base + OB_AH + aOff + (uint32_t)(mt * 16 * 144 + ks * 32);
                ldsm_x4(ah[mt], ad);
                ldsm_x4(al[mt], ad + (OB_AL - OB_AH));
            }
            #pragma unroll
            for (int nt2 = 0; nt2 < 2; nt2++) {
                uint32_t bd = base + OB_WH + bOff + (uint32_t)(ks * 16 * 144 + nt2 * 32);
                ldsm_x4_t(bh[nt2], bd);
                ldsm_x4_t(bl[nt2], bd + (OB_WL - OB_WH));
            }
            #pragma unroll
            for (int mt = 0; mt < 2; mt++) {
                #pragma unroll
                for (int nt = 0; nt < 4; nt++) {
                    const uint32_t* ph = &bh[nt >> 1][(nt & 1) * 2];
                    const uint32_t* pl = &bl[nt >> 1][(nt & 1) * 2];
                    mma_bf16(acc[mt][nt], ah[mt], ph);
                    mma_bf16(acc[mt][nt], ah[mt], pl);
                    mma_bf16(acc[mt][nt], al[mt], ph);
                }
            }
        }
        __syncthreads();
    }

    #pragma unroll
    for (int mt = 0; mt < 2; mt++) {
        int r0 = row0 + wr * 32 + mt * 16 + (lane >> 2);
        #pragma unroll
        for (int nt = 0; nt < 4; nt++) {
            int col = wc * 32 + nt * 8 + (lane & 3) * 2;
            if (r0 < n)
                *(float2*)&g_h2[(size_t)r0 * C_B + col] =
                    make_float2(acc[mt][nt][0], acc[mt][nt][1]);
            if (r0 + 8 < n)
                *(float2*)&g_h2[(size_t)(r0 + 8) * C_B + col] =
                    make_float2(acc[mt][nt][2], acc[mt][nt][3]);
        }
    }
    epilogue_stats<4>(acc, row0 + wr * 32, n, wc * 32, lane, g_sum2, g_sq2);
}

// ============== GEMM2 via mma.sync: h3 = act2(h2)[N,64] @ w2[64,256] ==============
#define G2_AH 0
#define G2_AL 18432
#define G2_BH 36864
#define G2_BL (36864 + 17408)
#define G2_SMEM (36864 + 2 * 17408)   // 71680

__global__ void __launch_bounds__(256) gemm2_mma_kernel(const float* __restrict__ w2, int n) {
    extern __shared__ char smem[];
    const uint32_t sb = smem_u32(smem);
    const int tid = threadIdx.x;
    const int wid = tid >> 5, lane = tid & 31;
    const int wr = wid & 3, wc = wid >> 2;
    const int row0 = blockIdx.x * 128;
    const int col0 = blockIdx.y * 128;

    // stage A with BN2+GELU+split
    #pragma unroll
    for (int j = 0; j < 8; j++) {
        int s = tid + 256 * j;
        int r = s >> 4, f4 = s & 15;
        int rr = row0 + r; if (rr >= n) rr = n - 1;
        float4 v = *(const float4*)(g_h2 + (size_t)rr * C_B + f4 * 4);
        int c = f4 * 4;
        v.x = gelu_exact(fmaf(g_a2[c],     v.x, g_c2[c]));
        v.y = gelu_exact(fmaf(g_a2[c + 1], v.y, g_c2[c + 1]));
        v.z = gelu_exact(fmaf(g_a2[c + 2], v.z, g_c2[c + 2]));
        v.w = gelu_exact(fmaf(g_a2[c + 3], v.w, g_c2[c + 3]));
        uint2 hi, lo; split4(v, &hi, &lo);
        *(uint2*)(smem + G2_AH + r * 144 + f4 * 8) = hi;
        *(uint2*)(smem + G2_AL + r * 144 + f4 * 8) = lo;
    }
    // stage B: w2[0..63][col0..col0+127]
    #pragma unroll
    for (int j = 0; j < 8; j++) {
        int s = tid + 256 * j;                // 0..2047
        int r = s >> 5, f4 = s & 31;
        float4 v = *(const float4*)(w2 + (size_t)r * C_IN + col0 + f4 * 4);
        uint2 hi, lo; split4(v, &hi, &lo);
        *(uint2*)(smem + G2_BH + r * 272 + f4 * 8) = hi;
        *(uint2*)(smem + G2_BL + r * 272 + f4 * 8) = lo;
    }
    __syncthreads();

    float acc[2][8][4] = {};
    const uint32_t aOff = (uint32_t)((wr * 32 + (lane & 15)) * 144 + (lane >> 4) * 16);
    const uint32_t bOff = (uint32_t)((lane & 15) * 272 + (wc * 64 + (lane >> 4) * 8) * 2);

    #pragma unroll
    for (int ks = 0; ks < 4; ks++) {
        uint32_t ah[2][4], al[2][4], bh[4][4], bl[4][4];
        #pragma unroll
        for (int mt = 0; mt < 2; mt++) {
            uint32_t ad = sb + G2_AH + aOff + (uint32_t)(mt * 16 * 144 + ks * 32);
            ldsm_x4(ah[mt], ad);
            ldsm_x4(al[mt], ad + (G2_AL - G2_AH));
        }
        #pragma unroll
        for (int nt2 = 0; nt2 < 4; nt2++) {
            uint32_t bd = sb + G2_BH + bOff + (uint32_t)(ks * 16 * 272 + nt2 * 32);
            ldsm_x4_t(bh[nt2], bd);
            ldsm_x4_t(bl[nt2], bd + (G2_BL - G2_BH));
        }
        #pragma unroll
        for (int mt = 0; mt < 2; mt++) {
            #pragma unroll
            for (int nt = 0; nt < 8; nt++) {
                const uint32_t* ph = &bh[nt >> 1][(nt & 1) * 2];
                const uint32_t* pl = &bl[nt >> 1][(nt & 1) * 2];
                mma_bf16(acc[mt][nt], ah[mt], ph);
                mma_bf16(acc[mt][nt], ah[mt], pl);
                mma_bf16(acc[mt][nt], al[mt], ph);
            }
        }
    }

    #pragma unroll
    for (int mt = 0; mt < 2; mt++) {
        int r0 = row0 + wr * 32 + mt * 16 + (lane >> 2);
        #pragma unroll
        for (int nt = 0; nt < 8; nt++) {
            int col = col0 + wc * 64 + nt * 8 + (lane & 3) * 2;
            if (r0 < n)
                *(float2*)&g_h3[(size_t)r0 * C_IN + col] =
                    make_float2(acc[mt][nt][0], acc[mt][nt][1]);
            if (r0 + 8 < n)
                *(float2*)&g_h3[(size_t)(r0 + 8) * C_IN + col] =
                    make_float2(acc[mt][nt][2], acc[mt][nt][3]);
        }
    }
    epilogue_stats<8>(acc, row0 + wr * 32, n, col0 + wc * 64, lane, g_sum3, g_sq3);
}

// ---------------- epilogue: out = elu(bn3(h3) + data), 8 floats/thread ----------------
__global__ void final_kernel(const float* __restrict__ data,
                             float* __restrict__ out, long long total) {
    long long i = ((long long)blockIdx.x * blockDim.x + threadIdx.x) * 8;
    if (i >= total) return;
    #pragma unroll
    for (int half = 0; half < 2; half++) {
        long long ii = i + half * 4;
        float4 h = *(const float4*)&g_h3[ii];
        float4 d = *(const float4*)&data[ii];
        int c = (int)(ii & (C_IN - 1));
        float x;
        x = fmaf(g_a3[c],     h.x, g_c3[c]) + d.x; h.x = x > 0.f ? x : expm1f(x);
        x = fmaf(g_a3[c + 1], h.y, g_c3[c + 1]) + d.y; h.y = x > 0.f ? x : expm1f(x);
        x = fmaf(g_a3[c + 2], h.z, g_c3[c + 2]) + d.z; h.z = x > 0.f ? x : expm1f(x);
        x = fmaf(g_a3[c + 3], h.w, g_c3[c + 3]) + d.w; h.w = x > 0.f ? x : expm1f(x);
        *(float4*)&out[ii] = h;
    }
}

// ---------------- launch ----------------
extern "C" void kernel_launch(void* const* d_in, const int* in_sizes, int n_in,
                              void* d_out, int out_size) {
    const float* data  = (const float*)d_in[0];
    const int*   neigh = (const int*)d_in[1];
    const float* w1 = (const float*)d_in[2];
    const float* g1 = (const float*)d_in[3];
    const float* b1 = (const float*)d_in[4];
    const float* w3 = (const float*)d_in[5];
    const float* g3 = (const float*)d_in[6];
    const float* b3 = (const float*)d_in[7];
    const float* w2 = (const float*)d_in[8];
    const float* g2 = (const float*)d_in[9];
    const float* b2 = (const float*)d_in[10];
    float* out = (float*)d_out;

    const int n = in_sizes[0] / C_IN;
    const float inv_n = 1.0f / (float)n;
    const int nblk128 = (n + 127) / 128;
    const long long tot_b = (long long)n * C_B;
    const long long tot_c = (long long)n * C_IN;

    cudaFuncSetAttribute(gemm1_mma_kernel,
                         cudaFuncAttributeMaxDynamicSharedMemorySize, G1_SMEM);
    cudaFuncSetAttribute(octconv_mma_kernel,
                         cudaFuncAttributeMaxDynamicSharedMemorySize, OCT_SMEM);
    cudaFuncSetAttribute(gemm2_mma_kernel,
                         cudaFuncAttributeMaxDynamicSharedMemorySize, G2_SMEM);

    zero_stats_kernel<<<1, 256>>>();
    w3_split_kernel<<<(K_TAP * C_B * C_B + 255) / 256, 256>>>(w3);

    gemm1_mma_kernel<<<nblk128, 256, G1_SMEM>>>(data, w1, n);
    bnfin1_kernel<<<1, C_B>>>(g1, b1, inv_n);
    act1_split_kernel<<<(int)((tot_b / 4 + 255) / 256), 256>>>(tot_b);

    octconv_mma_kernel<<<nblk128, 256, OCT_SMEM>>>(neigh, n);
    bnfin2_kernel<<<1, C_B>>>(g3, b3, inv_n);

    gemm2_mma_kernel<<<dim3(nblk128, 2), 256, G2_SMEM>>>(w2, n);
    bnfin3_kernel<<<1, C_IN>>>(g2, b2, inv_n);

    final_kernel<<<(int)((tot_c / 8 + 255) / 256), 256>>>(data, out, tot_c);
}

// round 12
// speedup vs baseline: 1.4376x; 1.4376x over previous
#include <cuda_runtime.h>
#include <cuda_fp16.h>
#include <math.h>
#include <stdint.h>

#define C_IN   256
#define C_B    64
#define K_TAP  27
#define N_MAX  200000
#define BN_EPS 1e-3f

// ---------------- scratch (device globals; no allocation) ----------------
__device__ float g_h1[(size_t)N_MAX * C_B];   // conv1x1a raw
__device__ float g_h2[(size_t)N_MAX * C_B];   // octree conv raw
__device__ float g_h3[(size_t)N_MAX * C_IN];  // conv1x1b raw

__device__ __half g_h1h[(size_t)N_MAX * C_B];  // act1 (fp16 rounded)
__device__ __half g_w3h[K_TAP * C_B * C_B];    // w3 [k][c][d] hi
__device__ __half g_w3l[K_TAP * C_B * C_B];    // lo

__device__ float g_sum1[C_B],  g_sq1[C_B],  g_a1[C_B],  g_c1[C_B];
__device__ float g_sum2[C_B],  g_sq2[C_B],  g_a2[C_B],  g_c2[C_B];
__device__ float g_sum3[C_IN], g_sq3[C_IN], g_a3[C_IN], g_c3[C_IN];

__device__ __forceinline__ float gelu_exact(float x) {
    return 0.5f * x * (1.0f + erff(x * 0.70710678118654752440f));
}

// ---------------- mma/ldsm/cp.async helpers ----------------
__device__ __forceinline__ uint32_t smem_u32(const void* p) {
    uint32_t a;
    asm("{ .reg .u64 t; cvta.to.shared.u64 t, %1; cvt.u32.u64 %0, t; }"
        : "=r"(a) : "l"(p));
    return a;
}
__device__ __forceinline__ void ldsm_x4(uint32_t* r, uint32_t addr) {
    asm volatile("ldmatrix.sync.aligned.m8n8.x4.shared.b16 {%0,%1,%2,%3}, [%4];"
                 : "=r"(r[0]), "=r"(r[1]), "=r"(r[2]), "=r"(r[3]) : "r"(addr));
}
__device__ __forceinline__ void ldsm_x4_t(uint32_t* r, uint32_t addr) {
    asm volatile("ldmatrix.sync.aligned.m8n8.x4.trans.shared.b16 {%0,%1,%2,%3}, [%4];"
                 : "=r"(r[0]), "=r"(r[1]), "=r"(r[2]), "=r"(r[3]) : "r"(addr));
}
__device__ __forceinline__ void mma_f16(float* d, const uint32_t* a, const uint32_t* b) {
    asm volatile(
        "mma.sync.aligned.m16n8k16.row.col.f32.f16.f16.f32 "
        "{%0,%1,%2,%3}, {%4,%5,%6,%7}, {%8,%9}, {%0,%1,%2,%3};"
        : "+f"(d[0]), "+f"(d[1]), "+f"(d[2]), "+f"(d[3])
        : "r"(a[0]), "r"(a[1]), "r"(a[2]), "r"(a[3]), "r"(b[0]), "r"(b[1]));
}
__device__ __forceinline__ void cp16(uint32_t dst, const void* src) {
    asm volatile("cp.async.cg.shared.global [%0], [%1], 16;" :: "r"(dst), "l"(src));
}
__device__ __forceinline__ void cp_commit() {
    asm volatile("cp.async.commit_group;" ::: "memory");
}

__device__ __forceinline__ uint32_t hpack(__half a, __half b) {
    unsigned short ua = *(unsigned short*)&a, ub = *(unsigned short*)&b;
    return (uint32_t)ua | ((uint32_t)ub << 16);
}
// round 4 floats to fp16 (hi only)
__device__ __forceinline__ uint2 round4h(float4 v) {
    uint2 r;
    r.x = hpack(__float2half_rn(v.x), __float2half_rn(v.y));
    r.y = hpack(__float2half_rn(v.z), __float2half_rn(v.w));
    return r;
}
// split 4 floats into fp16 hi + lo
__device__ __forceinline__ void split4h(float4 v, uint2* hi, uint2* lo) {
    __half h0 = __float2half_rn(v.x), h1 = __float2half_rn(v.y);
    __half h2 = __float2half_rn(v.z), h3 = __float2half_rn(v.w);
    __half l0 = __float2half_rn(v.x - __half2float(h0));
    __half l1 = __float2half_rn(v.y - __half2float(h1));
    __half l2 = __float2half_rn(v.z - __half2float(h2));
    __half l3 = __float2half_rn(v.w - __half2float(h3));
    hi->x = hpack(h0, h1); hi->y = hpack(h2, h3);
    lo->x = hpack(l0, l1); lo->y = hpack(l2, l3);
}

// ---------------- stats reset ----------------
__global__ void zero_stats_kernel() {
    int t = threadIdx.x;
    if (t < C_B)  { g_sum1[t] = 0.f; g_sq1[t] = 0.f; g_sum2[t] = 0.f; g_sq2[t] = 0.f; }
    if (t < C_IN) { g_sum3[t] = 0.f; g_sq3[t] = 0.f; }
}

// ---------------- per-channel stats ----------------
template<int CC>
__device__ __forceinline__ void stats_body(const float* __restrict__ x, int n,
                                           float* __restrict__ sums,
                                           float* __restrict__ sqs) {
    __shared__ float sm[256], qm[256];
    const int tid = threadIdx.x;
    const int col = tid % CC;
    const int rid = tid / CC;
    const int rpt = 256 / CC;

    long long rows_per_blk = (n + gridDim.x - 1) / gridDim.x;
    long long r0 = (long long)blockIdx.x * rows_per_blk;
    long long r1 = r0 + rows_per_blk; if (r1 > n) r1 = n;

    float s = 0.f, q = 0.f;
    for (long long r = r0 + rid; r < r1; r += rpt) {
        float v = x[r * CC + col];
        s += v; q += v * v;
    }
    sm[tid] = s; qm[tid] = q;
    __syncthreads();
    for (int off = 128; off >= CC; off >>= 1) {
        if (tid < off) { sm[tid] += sm[tid + off]; qm[tid] += qm[tid + off]; }
        __syncthreads();
    }
    if (tid < CC) {
        atomicAdd(&sums[tid], sm[tid]);
        atomicAdd(&sqs[tid],  qm[tid]);
    }
}

__global__ void stats1_kernel(int n) { stats_body<C_B >(g_h1, n, g_sum1, g_sq1); }
__global__ void stats2_kernel(int n) { stats_body<C_B >(g_h2, n, g_sum2, g_sq2); }
__global__ void stats3_kernel(int n) { stats_body<C_IN>(g_h3, n, g_sum3, g_sq3); }

// ---------------- BN finalize ----------------
__device__ __forceinline__ void bnfin_body(const float* sums, const float* sqs,
                                           const float* __restrict__ g,
                                           const float* __restrict__ b,
                                           float* a, float* c, float inv_n) {
    int t = threadIdx.x;
    float m = sums[t] * inv_n;
    float v = sqs[t] * inv_n - m * m;
    if (v < 0.f) v = 0.f;
    float s = g[t] * rsqrtf(v + BN_EPS);
    a[t] = s;
    c[t] = b[t] - m * s;
}
__global__ void bnfin1_kernel(const float* __restrict__ g, const float* __restrict__ b, float inv_n)
{ bnfin_body(g_sum1, g_sq1, g, b, g_a1, g_c1, inv_n); }
__global__ void bnfin2_kernel(const float* __restrict__ g, const float* __restrict__ b, float inv_n)
{ bnfin_body(g_sum2, g_sq2, g, b, g_a2, g_c2, inv_n); }
__global__ void bnfin3_kernel(const float* __restrict__ g, const float* __restrict__ b, float inv_n)
{ bnfin_body(g_sum3, g_sq3, g, b, g_a3, g_c3, inv_n); }

// ---------------- act1: BN+GELU, write fp16 ----------------
__global__ void act1_kernel(long long total) {
    long long i = ((long long)blockIdx.x * blockDim.x + threadIdx.x) * 4;
    if (i >= total) return;
    float4 v = *(const float4*)&g_h1[i];
    int c = (int)(i & (C_B - 1));
    v.x = gelu_exact(fmaf(g_a1[c],     v.x, g_c1[c]));
    v.y = gelu_exact(fmaf(g_a1[c + 1], v.y, g_c1[c + 1]));
    v.z = gelu_exact(fmaf(g_a1[c + 2], v.z, g_c1[c + 2]));
    v.w = gelu_exact(fmaf(g_a1[c + 3], v.w, g_c1[c + 3]));
    *(uint2*)((unsigned short*)g_h1h + i) = round4h(v);
}

// ---------------- w3 split (keep [k][c][d] layout), fp16 hi/lo ----------------
__global__ void w3_split_kernel(const float* __restrict__ w3) {
    int i = blockIdx.x * blockDim.x + threadIdx.x;
    if (i >= K_TAP * C_B * C_B) return;
    float v = w3[i];
    __half h = __float2half_rn(v);
    __half l = __float2half_rn(v - __half2float(h));
    g_w3h[i] = h;
    g_w3l[i] = l;
}

// ============== GEMM1 via mma.sync fp16: h1 = data[N,256] @ w1[256,64] ==============
// A rounded to fp16 (2-term on B only): acc += Ah*Bh + Ah*Bl
#define G1_A  0
#define G1_BH 18432
#define G1_BL 27648
#define G1_SMEM 36864

__global__ void __launch_bounds__(256) gemm1_mma_kernel(const float* __restrict__ data,
                                                        const float* __restrict__ w1, int n) {
    extern __shared__ char smem[];
    const uint32_t sb = smem_u32(smem);
    const int tid = threadIdx.x;
    const int wid = tid >> 5, lane = tid & 31;
    const int wr = wid & 3, wc = wid >> 2;
    const int row0 = blockIdx.x * 128;

    float acc[2][4][4] = {};
    const uint32_t aOff = (uint32_t)((wr * 32 + (lane & 15)) * 144 + (lane >> 4) * 16);
    const uint32_t bOff = (uint32_t)((lane & 15) * 144 + (wc * 32 + (lane >> 4) * 8) * 2);

    for (int kb = 0; kb < C_IN; kb += 64) {
        // stage A: 128 rows x 64 k (fp16)
        #pragma unroll
        for (int j = 0; j < 8; j++) {
            int s = tid + 256 * j;
            int r = s >> 4, f4 = s & 15;
            int rr = row0 + r; if (rr >= n) rr = n - 1;
            float4 v = *(const float4*)(data + (size_t)rr * C_IN + kb + f4 * 4);
            *(uint2*)(smem + G1_A + r * 144 + f4 * 8) = round4h(v);
        }
        // stage B: 64 rows x 64 cols (fp16 hi/lo)
        #pragma unroll
        for (int j = 0; j < 4; j++) {
            int s = tid + 256 * j;
            int r = s >> 4, f4 = s & 15;
            float4 v = *(const float4*)(w1 + (size_t)(kb + r) * C_B + f4 * 4);
            uint2 hi, lo; split4h(v, &hi, &lo);
            *(uint2*)(smem + G1_BH + r * 144 + f4 * 8) = hi;
            *(uint2*)(smem + G1_BL + r * 144 + f4 * 8) = lo;
        }
        __syncthreads();

        #pragma unroll
        for (int ks = 0; ks < 4; ks++) {
            uint32_t ah[2][4], bh[2][4], bl[2][4];
            #pragma unroll
            for (int mt = 0; mt < 2; mt++)
                ldsm_x4(ah[mt], sb + G1_A + aOff + (uint32_t)(mt * 16 * 144 + ks * 32));
            #pragma unroll
            for (int nt2 = 0; nt2 < 2; nt2++) {
                uint32_t bd = sb + G1_BH + bOff + (uint32_t)(ks * 16 * 144 + nt2 * 32);
                ldsm_x4_t(bh[nt2], bd);
                ldsm_x4_t(bl[nt2], bd + (G1_BL - G1_BH));
            }
            #pragma unroll
            for (int mt = 0; mt < 2; mt++) {
                #pragma unroll
                for (int nt = 0; nt < 4; nt++) {
                    const uint32_t* ph = &bh[nt >> 1][(nt & 1) * 2];
                    const uint32_t* pl = &bl[nt >> 1][(nt & 1) * 2];
                    mma_f16(acc[mt][nt], ah[mt], ph);
                    mma_f16(acc[mt][nt], ah[mt], pl);
                }
            }
        }
        __syncthreads();
    }

    #pragma unroll
    for (int mt = 0; mt < 2; mt++) {
        int r0 = row0 + wr * 32 + mt * 16 + (lane >> 2);
        #pragma unroll
        for (int nt = 0; nt < 4; nt++) {
            int col = wc * 32 + nt * 8 + (lane & 3) * 2;
            if (r0 < n)
                *(float2*)&g_h1[(size_t)r0 * C_B + col] =
                    make_float2(acc[mt][nt][0], acc[mt][nt][1]);
            if (r0 + 8 < n)
                *(float2*)&g_h1[(size_t)(r0 + 8) * C_B + col] =
                    make_float2(acc[mt][nt][2], acc[mt][nt][3]);
        }
    }
}

// ============== octree conv via mma.sync fp16 + cp.async double buffering ==============
#define OB_A  0
#define OB_WH 18432
#define OB_WL 27648
#define OB_SZ 36864
#define OFF_IDX 0
#define OFF_BUF 13824
#define OCT_SMEM (OFF_BUF + 2 * OB_SZ)   // 87552

__device__ __forceinline__ void issue_tap(uint32_t sb, int buf, int k,
                                          const int* sIdx, int tid) {
    const uint32_t base = sb + OFF_BUF + buf * OB_SZ;
    const int* idx = sIdx + (k << 7);
    #pragma unroll
    for (int j = 0; j < 4; j++) {
        int cid = tid + 256 * j;              // 0..1023
        int r = cid >> 3, q = cid & 7;
        int gr = idx[r];
        cp16(base + OB_A + (uint32_t)(r * 144 + q * 16),
             g_h1h + (size_t)gr * C_B + q * 8);
    }
    #pragma unroll
    for (int j = 0; j < 2; j++) {
        int cid = tid + 256 * j;              // 0..511
        int r = cid >> 3, q = cid & 7;
        uint32_t d = base + (uint32_t)(r * 144 + q * 16);
        cp16(d + OB_WH, g_w3h + (size_t)k * 4096 + cid * 8);
        cp16(d + OB_WL, g_w3l + (size_t)k * 4096 + cid * 8);
    }
}

__global__ void __launch_bounds__(256) octconv_mma_kernel(const int* __restrict__ neigh,
                                                          int n) {
    extern __shared__ char smem[];
    const uint32_t sb = smem_u32(smem);
    const int tid = threadIdx.x;
    const int wid = tid >> 5, lane = tid & 31;
    const int wr = wid & 3, wc = wid >> 2;
    const int row0 = blockIdx.x * 128;

    int* sIdx = (int*)(smem + OFF_IDX);
    for (int i = tid; i < K_TAP * 128; i += 256) {
        int r = i / K_TAP, k = i - r * K_TAP;
        int nr = row0 + r;
        sIdx[k * 128 + r] = (nr < n) ? neigh[(size_t)nr * K_TAP + k] : 0;
    }
    __syncthreads();

    issue_tap(sb, 0, 0, sIdx, tid);
    cp_commit();

    float acc[2][4][4] = {};
    const uint32_t aOff = (uint32_t)((wr * 32 + (lane & 15)) * 144 + (lane >> 4) * 16);
    const uint32_t bOff = (uint32_t)((lane & 15) * 144 + (wc * 32 + (lane >> 4) * 8) * 2);

    for (int k = 0; k < K_TAP; k++) {
        const int b = k & 1;
        if (k + 1 < K_TAP) {
            issue_tap(sb, b ^ 1, k + 1, sIdx, tid);
            cp_commit();
            asm volatile("cp.async.wait_group 1;" ::: "memory");
        } else {
            asm volatile("cp.async.wait_group 0;" ::: "memory");
        }
        __syncthreads();

        const uint32_t base = sb + OFF_BUF + b * OB_SZ;
        #pragma unroll
        for (int ks = 0; ks < 4; ks++) {
            uint32_t ah[2][4], bh[2][4], bl[2][4];
            #pragma unroll
            for (int mt = 0; mt < 2; mt++)
                ldsm_x4(ah[mt], base + OB_A + aOff + (uint32_t)(mt * 16 * 144 + ks * 32));
            #pragma unroll
            for (int nt2 = 0; nt2 < 2; nt2++) {
                uint32_t bd = base + OB_WH + bOff + (uint32_t)(ks * 16 * 144 + nt2 * 32);
                ldsm_x4_t(bh[nt2], bd);
                ldsm_x4_t(bl[nt2], bd + (OB_WL - OB_WH));
            }
            #pragma unroll
            for (int mt = 0; mt < 2; mt++) {
                #pragma unroll
                for (int nt = 0; nt < 4; nt++) {
                    const uint32_t* ph = &bh[nt >> 1][(nt & 1) * 2];
                    const uint32_t* pl = &bl[nt >> 1][(nt & 1) * 2];
                    mma_f16(acc[mt][nt], ah[mt], ph);
                    mma_f16(acc[mt][nt], ah[mt], pl);
                }
            }
        }
        __syncthreads();
    }

    #pragma unroll
    for (int mt = 0; mt < 2; mt++) {
        int r0 = row0 + wr * 32 + mt * 16 + (lane >> 2);
        #pragma unroll
        for (int nt = 0; nt < 4; nt++) {
            int col = wc * 32 + nt * 8 + (lane & 3) * 2;
            if (r0 < n)
                *(float2*)&g_h2[(size_t)r0 * C_B + col] =
                    make_float2(acc[mt][nt][0], acc[mt][nt][1]);
            if (r0 + 8 < n)
                *(float2*)&g_h2[(size_t)(r0 + 8) * C_B + col] =
                    make_float2(acc[mt][nt][2], acc[mt][nt][3]);
        }
    }
}

// ============== GEMM2 via mma.sync fp16: h3 = act2(h2)[N,64] @ w2[64,256] ==============
#define G2_A  0
#define G2_BH 18432
#define G2_BL (18432 + 17408)
#define G2_SMEM (18432 + 2 * 17408)   // 53248

__global__ void __launch_bounds__(256) gemm2_mma_kernel(const float* __restrict__ w2, int n) {
    extern __shared__ char smem[];
    const uint32_t sb = smem_u32(smem);
    const int tid = threadIdx.x;
    const int wid = tid >> 5, lane = tid & 31;
    const int wr = wid & 3, wc = wid >> 2;
    const int row0 = blockIdx.x * 128;
    const int col0 = blockIdx.y * 128;

    // stage A with BN2+GELU, rounded to fp16
    #pragma unroll
    for (int j = 0; j < 8; j++) {
        int s = tid + 256 * j;
        int r = s >> 4, f4 = s & 15;
        int rr = row0 + r; if (rr >= n) rr = n - 1;
        float4 v = *(const float4*)(g_h2 + (size_t)rr * C_B + f4 * 4);
        int c = f4 * 4;
        v.x = gelu_exact(fmaf(g_a2[c],     v.x, g_c2[c]));
        v.y = gelu_exact(fmaf(g_a2[c + 1], v.y, g_c2[c + 1]));
        v.z = gelu_exact(fmaf(g_a2[c + 2], v.z, g_c2[c + 2]));
        v.w = gelu_exact(fmaf(g_a2[c + 3], v.w, g_c2[c + 3]));
        *(uint2*)(smem + G2_A + r * 144 + f4 * 8) = round4h(v);
    }
    // stage B: w2[0..63][col0..col0+127] (fp16 hi/lo, row stride 272 B)
    #pragma unroll
    for (int j = 0; j < 8; j++) {
        int s = tid + 256 * j;                // 0..2047
        int r = s >> 5, f4 = s & 31;
        float4 v = *(const float4*)(w2 + (size_t)r * C_IN + col0 + f4 * 4);
        uint2 hi, lo; split4h(v, &hi, &lo);
        *(uint2*)(smem + G2_BH + r * 272 + f4 * 8) = hi;
        *(uint2*)(smem + G2_BL + r * 272 + f4 * 8) = lo;
    }
    __syncthreads();

    float acc[2][8][4] = {};
    const uint32_t aOff = (uint32_t)((wr * 32 + (lane & 15)) * 144 + (lane >> 4) * 16);
    const uint32_t bOff = (uint32_t)((lane & 15) * 272 + (wc * 64 + (lane >> 4) * 8) * 2);

    #pragma unroll
    for (int ks = 0; ks < 4; ks++) {
        uint32_t ah[2][4], bh[4][4], bl[4][4];
        #pragma unroll
        for (int mt = 0; mt < 2; mt++)
            ldsm_x4(ah[mt], sb + G2_A + aOff + (uint32_t)(mt * 16 * 144 + ks * 32));
        #pragma unroll
        for (int nt2 = 0; nt2 < 4; nt2++) {
            uint32_t bd = sb + G2_BH + bOff + (uint32_t)(ks * 16 * 272 + nt2 * 32);
            ldsm_x4_t(bh[nt2], bd);
            ldsm_x4_t(bl[nt2], bd + (G2_BL - G2_BH));
        }
        #pragma unroll
        for (int mt = 0; mt < 2; mt++) {
            #pragma unroll
            for (int nt = 0; nt < 8; nt++) {
                const uint32_t* ph = &bh[nt >> 1][(nt & 1) * 2];
                const uint32_t* pl = &bl[nt >> 1][(nt & 1) * 2];
                mma_f16(acc[mt][nt], ah[mt], ph);
                mma_f16(acc[mt][nt], ah[mt], pl);
            }
        }
    }

    #pragma unroll
    for (int mt = 0; mt < 2; mt++) {
        int r0 = row0 + wr * 32 + mt * 16 + (lane >> 2);
        #pragma unroll
        for (int nt = 0; nt < 8; nt++) {
            int col = col0 + wc * 64 + nt * 8 + (lane & 3) * 2;
            if (r0 < n)
                *(float2*)&g_h3[(size_t)r0 * C_IN + col] =
                    make_float2(acc[mt][nt][0], acc[mt][nt][1]);
            if (r0 + 8 < n)
                *(float2*)&g_h3[(size_t)(r0 + 8) * C_IN + col] =
                    make_float2(acc[mt][nt][2], acc[mt][nt][3]);
        }
    }
}

// ---------------- epilogue: out = elu(bn3(h3) + data) ----------------
__global__ void final_kernel(const float* __restrict__ data,
                             float* __restrict__ out, long long total) {
    long long i = ((long long)blockIdx.x * blockDim.x + threadIdx.x) * 4;
    if (i >= total) return;
    float4 h = *(const float4*)&g_h3[i];
    float4 d = *(const float4*)&data[i];
    int c = (int)(i & (C_IN - 1));
    float x;
    x = fmaf(g_a3[c],     h.x, g_c3[c]) + d.x; h.x = x > 0.f ? x : expm1f(x);
    x = fmaf(g_a3[c + 1], h.y, g_c3[c + 1]) + d.y; h.y = x > 0.f ? x : expm1f(x);
    x = fmaf(g_a3[c + 2], h.z, g_c3[c + 2]) + d.z; h.z = x > 0.f ? x : expm1f(x);
    x = fmaf(g_a3[c + 3], h.w, g_c3[c + 3]) + d.w; h.w = x > 0.f ? x : expm1f(x);
    *(float4*)&out[i] = h;
}

// ---------------- launch ----------------
extern "C" void kernel_launch(void* const* d_in, const int* in_sizes, int n_in,
                              void* d_out, int out_size) {
    const float* data  = (const float*)d_in[0];
    const int*   neigh = (const int*)d_in[1];
    const float* w1 = (const float*)d_in[2];
    const float* g1 = (const float*)d_in[3];
    const float* b1 = (const float*)d_in[4];
    const float* w3 = (const float*)d_in[5];
    const float* g3 = (const float*)d_in[6];
    const float* b3 = (const float*)d_in[7];
    const float* w2 = (const float*)d_in[8];
    const float* g2 = (const float*)d_in[9];
    const float* b2 = (const float*)d_in[10];
    float* out = (float*)d_out;

    const int n = in_sizes[0] / C_IN;
    const float inv_n = 1.0f / (float)n;
    const int nblk128 = (n + 127) / 128;
    const long long tot_b = (long long)n * C_B;
    const long long tot_c = (long long)n * C_IN;

    cudaFuncSetAttribute(gemm1_mma_kernel,
                         cudaFuncAttributeMaxDynamicSharedMemorySize, G1_SMEM);
    cudaFuncSetAttribute(octconv_mma_kernel,
                         cudaFuncAttributeMaxDynamicSharedMemorySize, OCT_SMEM);
    cudaFuncSetAttribute(gemm2_mma_kernel,
                         cudaFuncAttributeMaxDynamicSharedMemorySize, G2_SMEM);

    zero_stats_kernel<<<1, 256>>>();
    w3_split_kernel<<<(K_TAP * C_B * C_B + 255) / 256, 256>>>(w3);

    gemm1_mma_kernel<<<nblk128, 256, G1_SMEM>>>(data, w1, n);
    stats1_kernel<<<512, 256>>>(n);
    bnfin1_kernel<<<1, C_B>>>(g1, b1, inv_n);
    act1_kernel<<<(int)((tot_b / 4 + 255) / 256), 256>>>(tot_b);

    octconv_mma_kernel<<<nblk128, 256, OCT_SMEM>>>(neigh, n);
    stats2_kernel<<<512, 256>>>(n);
    bnfin2_kernel<<<1, C_B>>>(g3, b3, inv_n);

    gemm2_mma_kernel<<<dim3(nblk128, 2), 256, G2_SMEM>>>(w2, n);
    stats3_kernel<<<512, 256>>>(n);
    bnfin3_kernel<<<1, C_IN>>>(g2, b2, inv_n);

    final_kernel<<<(int)((tot_c / 4 + 255) / 256), 256>>>(data, out, tot_c);
}

// round 13
// speedup vs baseline: 1.6481x; 1.1465x over previous
#include <cuda_runtime.h>
#include <cuda_fp16.h>
#include <math.h>
#include <stdint.h>

#define C_IN   256
#define C_B    64
#define K_TAP  27
#define N_MAX  200000
#define MAXB   1600
#define BN_EPS 1e-3f

// ---------------- scratch (device globals; no allocation) ----------------
__device__ float g_h1[(size_t)N_MAX * C_B];   // conv1x1a raw
__device__ float g_h2[(size_t)N_MAX * C_B];   // octree conv raw
__device__ __half g_h3h[(size_t)N_MAX * C_IN]; // conv1x1b raw (fp16)

__device__ __half g_h1h[(size_t)N_MAX * C_B];  // act1 (fp16 rounded)
__device__ __half g_w3h[K_TAP * C_B * C_B];    // w3 [k][c][d] hi
__device__ __half g_w3l[K_TAP * C_B * C_B];    // lo

__device__ float g_a1[C_B],  g_c1[C_B];
__device__ float g_a2[C_B],  g_c2[C_B];
__device__ float g_a3[C_IN], g_c3[C_IN];

// per-block stats partials (no atomics)
__device__ float g_p1s[MAXB * 64],  g_p1q[MAXB * 64];
__device__ float g_p2s[MAXB * 64],  g_p2q[MAXB * 64];
__device__ float g_p3s[2 * MAXB * 128], g_p3q[2 * MAXB * 128];

__device__ __forceinline__ float gelu_exact(float x) {
    return 0.5f * x * (1.0f + erff(x * 0.70710678118654752440f));
}

// ---------------- mma/ldsm/cp.async helpers ----------------
__device__ __forceinline__ uint32_t smem_u32(const void* p) {
    uint32_t a;
    asm("{ .reg .u64 t; cvta.to.shared.u64 t, %1; cvt.u32.u64 %0, t; }"
        : "=r"(a) : "l"(p));
    return a;
}
__device__ __forceinline__ void ldsm_x4(uint32_t* r, uint32_t addr) {
    asm volatile("ldmatrix.sync.aligned.m8n8.x4.shared.b16 {%0,%1,%2,%3}, [%4];"
                 : "=r"(r[0]), "=r"(r[1]), "=r"(r[2]), "=r"(r[3]) : "r"(addr));
}
__device__ __forceinline__ void ldsm_x4_t(uint32_t* r, uint32_t addr) {
    asm volatile("ldmatrix.sync.aligned.m8n8.x4.trans.shared.b16 {%0,%1,%2,%3}, [%4];"
                 : "=r"(r[0]), "=r"(r[1]), "=r"(r[2]), "=r"(r[3]) : "r"(addr));
}
__device__ __forceinline__ void mma_f16(float* d, const uint32_t* a, const uint32_t* b) {
    asm volatile(
        "mma.sync.aligned.m16n8k16.row.col.f32.f16.f16.f32 "
        "{%0,%1,%2,%3}, {%4,%5,%6,%7}, {%8,%9}, {%0,%1,%2,%3};"
        : "+f"(d[0]), "+f"(d[1]), "+f"(d[2]), "+f"(d[3])
        : "r"(a[0]), "r"(a[1]), "r"(a[2]), "r"(a[3]), "r"(b[0]), "r"(b[1]));
}
__device__ __forceinline__ void cp16(uint32_t dst, const void* src) {
    asm volatile("cp.async.cg.shared.global [%0], [%1], 16;" :: "r"(dst), "l"(src));
}
__device__ __forceinline__ void cp_commit() {
    asm volatile("cp.async.commit_group;" ::: "memory");
}

__device__ __forceinline__ uint32_t hpack(__half a, __half b) {
    unsigned short ua = *(unsigned short*)&a, ub = *(unsigned short*)&b;
    return (uint32_t)ua | ((uint32_t)ub << 16);
}
__device__ __forceinline__ uint2 round4h(float4 v) {
    uint2 r;
    r.x = hpack(__float2half_rn(v.x), __float2half_rn(v.y));
    r.y = hpack(__float2half_rn(v.z), __float2half_rn(v.w));
    return r;
}
__device__ __forceinline__ void split4h(float4 v, uint2* hi, uint2* lo) {
    __half h0 = __float2half_rn(v.x), h1 = __float2half_rn(v.y);
    __half h2 = __float2half_rn(v.z), h3 = __float2half_rn(v.w);
    __half l0 = __float2half_rn(v.x - __half2float(h0));
    __half l1 = __float2half_rn(v.y - __half2float(h1));
    __half l2 = __float2half_rn(v.z - __half2float(h2));
    __half l3 = __float2half_rn(v.w - __half2float(h3));
    hi->x = hpack(h0, h1); hi->y = hpack(h2, h3);
    lo->x = hpack(l0, l1); lo->y = hpack(l2, l3);
}

// ---------------- epilogue partial-stats: per-block column sum/sumsq ----------------
// NT = column tiles of 8 per warp. Block covers NT*16 cols (wc in {0,1}).
// Writes per-block partials to gS/gQ (length NT*16). NO atomics.
template<int NT>
__device__ __forceinline__ void epilogue_partials(const float acc[][NT][4],
                                                  int row0_w, int n,
                                                  int lane, int wid, int tid,
                                                  float* __restrict__ gS,
                                                  float* __restrict__ gQ) {
    __shared__ float sS[8][64], sQ[8][64];
    float cs[NT * 2], cq[NT * 2];
    #pragma unroll
    for (int i = 0; i < NT * 2; i++) { cs[i] = 0.f; cq[i] = 0.f; }
    #pragma unroll
    for (int mt = 0; mt < 2; mt++) {
        int r0 = row0_w + mt * 16 + (lane >> 2);
        bool v0 = r0 < n, v1 = (r0 + 8) < n;
        #pragma unroll
        for (int nt = 0; nt < NT; nt++) {
            #pragma unroll
            for (int j = 0; j < 2; j++) {
                float a0 = acc[mt][nt][j], a1 = acc[mt][nt][2 + j];
                if (v0) { cs[nt * 2 + j] += a0; cq[nt * 2 + j] += a0 * a0; }
                if (v1) { cs[nt * 2 + j] += a1; cq[nt * 2 + j] += a1 * a1; }
            }
        }
    }
    #pragma unroll
    for (int m = 4; m <= 16; m <<= 1) {
        #pragma unroll
        for (int i = 0; i < NT * 2; i++) {
            cs[i] += __shfl_xor_sync(0xffffffffu, cs[i], m);
            cq[i] += __shfl_xor_sync(0xffffffffu, cq[i], m);
        }
    }
    __syncthreads();
    if (lane < 4) {
        #pragma unroll
        for (int i = 0; i < NT * 2; i++) {
            int colw = (i >> 1) * 8 + lane * 2 + (i & 1);
            sS[wid][colw] = cs[i];
            sQ[wid][colw] = cq[i];
        }
    }
    __syncthreads();
    if (tid < NT * 16) {
        int grp = tid / (NT * 8);       // wc group
        int colw = tid % (NT * 8);
        float s = 0.f, q = 0.f;
        #pragma unroll
        for (int w = 0; w < 4; w++) {
            s += sS[grp * 4 + w][colw];
            q += sQ[grp * 4 + w][colw];
        }
        gS[tid] = s;
        gQ[tid] = q;
    }
}

// ---------------- reduce partials + BN finalize ----------------
__global__ void reduce_bnfin64(const float* __restrict__ pS, const float* __restrict__ pQ,
                               int nblk, const float* __restrict__ g,
                               const float* __restrict__ b,
                               float* __restrict__ a, float* __restrict__ c,
                               float inv_n) {
    __shared__ float sm[256], qm[256];
    int col = blockIdx.x, tid = threadIdx.x;
    float s = 0.f, q = 0.f;
    for (int bx = tid; bx < nblk; bx += 256) {
        s += pS[bx * 64 + col];
        q += pQ[bx * 64 + col];
    }
    sm[tid] = s; qm[tid] = q;
    __syncthreads();
    for (int off = 128; off; off >>= 1) {
        if (tid < off) { sm[tid] += sm[tid + off]; qm[tid] += qm[tid + off]; }
        __syncthreads();
    }
    if (tid == 0) {
        float m = sm[0] * inv_n;
        float v = qm[0] * inv_n - m * m;
        if (v < 0.f) v = 0.f;
        float sc = g[col] * rsqrtf(v + BN_EPS);
        a[col] = sc;
        c[col] = b[col] - m * sc;
    }
}
__global__ void reduce_bnfin256(const float* __restrict__ pS, const float* __restrict__ pQ,
                                int nblk, const float* __restrict__ g,
                                const float* __restrict__ b,
                                float* __restrict__ a, float* __restrict__ c,
                                float inv_n) {
    __shared__ float sm[256], qm[256];
    int col = blockIdx.x, tid = threadIdx.x;
    int by = col >> 7, colw = col & 127;
    const float* ps = pS + (size_t)by * MAXB * 128 + colw;
    const float* pq = pQ + (size_t)by * MAXB * 128 + colw;
    float s = 0.f, q = 0.f;
    for (int bx = tid; bx < nblk; bx += 256) {
        s += ps[bx * 128];
        q += pq[bx * 128];
    }
    sm[tid] = s; qm[tid] = q;
    __syncthreads();
    for (int off = 128; off; off >>= 1) {
        if (tid < off) { sm[tid] += sm[tid + off]; qm[tid] += qm[tid + off]; }
        __syncthreads();
    }
    if (tid == 0) {
        float m = sm[0] * inv_n;
        float v = qm[0] * inv_n - m * m;
        if (v < 0.f) v = 0.f;
        float sc = g[col] * rsqrtf(v + BN_EPS);
        a[col] = sc;
        c[col] = b[col] - m * sc;
    }
}

// ---------------- act1: BN+GELU, write fp16 ----------------
__global__ void act1_kernel(long long total) {
    long long i = ((long long)blockIdx.x * blockDim.x + threadIdx.x) * 4;
    if (i >= total) return;
    float4 v = *(const float4*)&g_h1[i];
    int c = (int)(i & (C_B - 1));
    v.x = gelu_exact(fmaf(g_a1[c],     v.x, g_c1[c]));
    v.y = gelu_exact(fmaf(g_a1[c + 1], v.y, g_c1[c + 1]));
    v.z = gelu_exact(fmaf(g_a1[c + 2], v.z, g_c1[c + 2]));
    v.w = gelu_exact(fmaf(g_a1[c + 3], v.w, g_c1[c + 3]));
    *(uint2*)((unsigned short*)g_h1h + i) = round4h(v);
}

// ---------------- w3 split (keep [k][c][d] layout), fp16 hi/lo ----------------
__global__ void w3_split_kernel(const float* __restrict__ w3) {
    int i = blockIdx.x * blockDim.x + threadIdx.x;
    if (i >= K_TAP * C_B * C_B) return;
    float v = w3[i];
    __half h = __float2half_rn(v);
    __half l = __float2half_rn(v - __half2float(h));
    g_w3h[i] = h;
    g_w3l[i] = l;
}

// ============== GEMM1 via mma.sync fp16: h1 = data[N,256] @ w1[256,64] ==============
#define G1_A  0
#define G1_BH 18432
#define G1_BL 27648
#define G1_SMEM 36864

__global__ void __launch_bounds__(256) gemm1_mma_kernel(const float* __restrict__ data,
                                                        const float* __restrict__ w1, int n) {
    extern __shared__ char smem[];
    const uint32_t sb = smem_u32(smem);
    const int tid = threadIdx.x;
    const int wid = tid >> 5, lane = tid & 31;
    const int wr = wid & 3, wc = wid >> 2;
    const int row0 = blockIdx.x * 128;

    float acc[2][4][4] = {};
    const uint32_t aOff = (uint32_t)((wr * 32 + (lane & 15)) * 144 + (lane >> 4) * 16);
    const uint32_t bOff = (uint32_t)((lane & 15) * 144 + (wc * 32 + (lane >> 4) * 8) * 2);

    for (int kb = 0; kb < C_IN; kb += 64) {
        #pragma unroll
        for (int j = 0; j < 8; j++) {
            int s = tid + 256 * j;
            int r = s >> 4, f4 = s & 15;
            int rr = row0 + r; if (rr >= n) rr = n - 1;
            float4 v = *(const float4*)(data + (size_t)rr * C_IN + kb + f4 * 4);
            *(uint2*)(smem + G1_A + r * 144 + f4 * 8) = round4h(v);
        }
        #pragma unroll
        for (int j = 0; j < 4; j++) {
            int s = tid + 256 * j;
            int r = s >> 4, f4 = s & 15;
            float4 v = *(const float4*)(w1 + (size_t)(kb + r) * C_B + f4 * 4);
            uint2 hi, lo; split4h(v, &hi, &lo);
            *(uint2*)(smem + G1_BH + r * 144 + f4 * 8) = hi;
            *(uint2*)(smem + G1_BL + r * 144 + f4 * 8) = lo;
        }
        __syncthreads();

        #pragma unroll
        for (int ks = 0; ks < 4; ks++) {
            uint32_t ah[2][4], bh[2][4], bl[2][4];
            #pragma unroll
            for (int mt = 0; mt < 2; mt++)
                ldsm_x4(ah[mt], sb + G1_A + aOff + (uint32_t)(mt * 16 * 144 + ks * 32));
            #pragma unroll
            for (int nt2 = 0; nt2 < 2; nt2++) {
                uint32_t bd = sb + G1_BH + bOff + (uint32_t)(ks * 16 * 144 + nt2 * 32);
                ldsm_x4_t(bh[nt2], bd);
                ldsm_x4_t(bl[nt2], bd + (G1_BL - G1_BH));
            }
            #pragma unroll
            for (int mt = 0; mt < 2; mt++) {
                #pragma unroll
                for (int nt = 0; nt < 4; nt++) {
                    const uint32_t* ph = &bh[nt >> 1][(nt & 1) * 2];
                    const uint32_t* pl = &bl[nt >> 1][(nt & 1) * 2];
                    mma_f16(acc[mt][nt], ah[mt], ph);
                    mma_f16(acc[mt][nt], ah[mt], pl);
                }
            }
        }
        __syncthreads();
    }

    #pragma unroll
    for (int mt = 0; mt < 2; mt++) {
        int r0 = row0 + wr * 32 + mt * 16 + (lane >> 2);
        #pragma unroll
        for (int nt = 0; nt < 4; nt++) {
            int col = wc * 32 + nt * 8 + (lane & 3) * 2;
            if (r0 < n)
                *(float2*)&g_h1[(size_t)r0 * C_B + col] =
                    make_float2(acc[mt][nt][0], acc[mt][nt][1]);
            if (r0 + 8 < n)
                *(float2*)&g_h1[(size_t)(r0 + 8) * C_B + col] =
                    make_float2(acc[mt][nt][2], acc[mt][nt][3]);
        }
    }
    epilogue_partials<4>(acc, row0 + wr * 32, n, lane, wid, tid,
                         g_p1s + (size_t)blockIdx.x * 64,
                         g_p1q + (size_t)blockIdx.x * 64);
}

// ============== octree conv via mma.sync fp16 + cp.async double buffering ==============
#define OB_A  0
#define OB_WH 18432
#define OB_WL 27648
#define OB_SZ 36864
#define OFF_IDX 0
#define OFF_BUF 13824
#define OCT_SMEM (OFF_BUF + 2 * OB_SZ)   // 87552

__device__ __forceinline__ void issue_tap(uint32_t sb, int buf, int k,
                                          const int* sIdx, int tid) {
    const uint32_t base = sb + OFF_BUF + buf * OB_SZ;
    const int* idx = sIdx + (k << 7);
    #pragma unroll
    for (int j = 0; j < 4; j++) {
        int cid = tid + 256 * j;              // 0..1023
        int r = cid >> 3, q = cid & 7;
        int gr = idx[r];
        cp16(base + OB_A + (uint32_t)(r * 144 + q * 16),
             g_h1h + (size_t)gr * C_B + q * 8);
    }
    #pragma unroll
    for (int j = 0; j < 2; j++) {
        int cid = tid + 256 * j;              // 0..511
        int r = cid >> 3, q = cid & 7;
        uint32_t d = base + (uint32_t)(r * 144 + q * 16);
        cp16(d + OB_WH, g_w3h + (size_t)k * 4096 + cid * 8);
        cp16(d + OB_WL, g_w3l + (size_t)k * 4096 + cid * 8);
    }
}

__global__ void __launch_bounds__(256) octconv_mma_kernel(const int* __restrict__ neigh,
                                                          int n) {
    extern __shared__ char smem[];
    const uint32_t sb = smem_u32(smem);
    const int tid = threadIdx.x;
    const int wid = tid >> 5, lane = tid & 31;
    const int wr = wid & 3, wc = wid >> 2;
    const int row0 = blockIdx.x * 128;

    int* sIdx = (int*)(smem + OFF_IDX);
    for (int i = tid; i < K_TAP * 128; i += 256) {
        int r = i / K_TAP, k = i - r * K_TAP;
        int nr = row0 + r;
        sIdx[k * 128 + r] = (nr < n) ? neigh[(size_t)nr * K_TAP + k] : 0;
    }
    __syncthreads();

    issue_tap(sb, 0, 0, sIdx, tid);
    cp_commit();

    float acc[2][4][4] = {};
    const uint32_t aOff = (uint32_t)((wr * 32 + (lane & 15)) * 144 + (lane >> 4) * 16);
    const uint32_t bOff = (uint32_t)((lane & 15) * 144 + (wc * 32 + (lane >> 4) * 8) * 2);

    for (int k = 0; k < K_TAP; k++) {
        const int b = k & 1;
        if (k + 1 < K_TAP) {
            issue_tap(sb, b ^ 1, k + 1, sIdx, tid);
            cp_commit();
            asm volatile("cp.async.wait_group 1;" ::: "memory");
        } else {
            asm volatile("cp.async.wait_group 0;" ::: "memory");
        }
        __syncthreads();

        const uint32_t base = sb + OFF_BUF + b * OB_SZ;
        #pragma unroll
        for (int ks = 0; ks < 4; ks++) {
            uint32_t ah[2][4], bh[2][4], bl[2][4];
            #pragma unroll
            for (int mt = 0; mt < 2; mt++)
                ldsm_x4(ah[mt], base + OB_A + aOff + (uint32_t)(mt * 16 * 144 + ks * 32));
            #pragma unroll
            for (int nt2 = 0; nt2 < 2; nt2++) {
                uint32_t bd = base + OB_WH + bOff + (uint32_t)(ks * 16 * 144 + nt2 * 32);
                ldsm_x4_t(bh[nt2], bd);
                ldsm_x4_t(bl[nt2], bd + (OB_WL - OB_WH));
            }
            #pragma unroll
            for (int mt = 0; mt < 2; mt++) {
                #pragma unroll
                for (int nt = 0; nt < 4; nt++) {
                    const uint32_t* ph = &bh[nt >> 1][(nt & 1) * 2];
                    const uint32_t* pl = &bl[nt >> 1][(nt & 1) * 2];
                    mma_f16(acc[mt][nt], ah[mt], ph);
                    mma_f16(acc[mt][nt], ah[mt], pl);
                }
            }
        }
        __syncthreads();
    }

    #pragma unroll
    for (int mt = 0; mt < 2; mt++) {
        int r0 = row0 + wr * 32 + mt * 16 + (lane >> 2);
        #pragma unroll
        for (int nt = 0; nt < 4; nt++) {
            int col = wc * 32 + nt * 8 + (lane & 3) * 2;
            if (r0 < n)
                *(float2*)&g_h2[(size_t)r0 * C_B + col] =
                    make_float2(acc[mt][nt][0], acc[mt][nt][1]);
            if (r0 + 8 < n)
                *(float2*)&g_h2[(size_t)(r0 + 8) * C_B + col] =
                    make_float2(acc[mt][nt][2], acc[mt][nt][3]);
        }
    }
    epilogue_partials<4>(acc, row0 + wr * 32, n, lane, wid, tid,
                         g_p2s + (size_t)blockIdx.x * 64,
                         g_p2q + (size_t)blockIdx.x * 64);
}

// ============== GEMM2 via mma.sync fp16: h3 = act2(h2)[N,64] @ w2[64,256] ==============
#define G2_A  0
#define G2_BH 18432
#define G2_BL (18432 + 17408)
#define G2_SMEM (18432 + 2 * 17408)   // 53248

__global__ void __launch_bounds__(256) gemm2_mma_kernel(const float* __restrict__ w2, int n) {
    extern __shared__ char smem[];
    const uint32_t sb = smem_u32(smem);
    const int tid = threadIdx.x;
    const int wid = tid >> 5, lane = tid & 31;
    const int wr = wid & 3, wc = wid >> 2;
    const int row0 = blockIdx.x * 128;
    const int col0 = blockIdx.y * 128;

    // stage A with BN2+GELU, rounded to fp16
    #pragma unroll
    for (int j = 0; j < 8; j++) {
        int s = tid + 256 * j;
        int r = s >> 4, f4 = s & 15;
        int rr = row0 + r; if (rr >= n) rr = n - 1;
        float4 v = *(const float4*)(g_h2 + (size_t)rr * C_B + f4 * 4);
        int c = f4 * 4;
        v.x = gelu_exact(fmaf(g_a2[c],     v.x, g_c2[c]));
        v.y = gelu_exact(fmaf(g_a2[c + 1], v.y, g_c2[c + 1]));
        v.z = gelu_exact(fmaf(g_a2[c + 2], v.z, g_c2[c + 2]));
        v.w = gelu_exact(fmaf(g_a2[c + 3], v.w, g_c2[c + 3]));
        *(uint2*)(smem + G2_A + r * 144 + f4 * 8) = round4h(v);
    }
    // stage B: w2[0..63][col0..col0+127] (fp16 hi/lo, row stride 272 B)
    #pragma unroll
    for (int j = 0; j < 8; j++) {
        int s = tid + 256 * j;                // 0..2047
        int r = s >> 5, f4 = s & 31;
        float4 v = *(const float4*)(w2 + (size_t)r * C_IN + col0 + f4 * 4);
        uint2 hi, lo; split4h(v, &hi, &lo);
        *(uint2*)(smem + G2_BH + r * 272 + f4 * 8) = hi;
        *(uint2*)(smem + G2_BL + r * 272 + f4 * 8) = lo;
    }
    __syncthreads();

    float acc[2][8][4] = {};
    const uint32_t aOff = (uint32_t)((wr * 32 + (lane & 15)) * 144 + (lane >> 4) * 16);
    const uint32_t bOff = (uint32_t)((lane & 15) * 272 + (wc * 64 + (lane >> 4) * 8) * 2);

    #pragma unroll
    for (int ks = 0; ks < 4; ks++) {
        uint32_t ah[2][4], bh[4][4], bl[4][4];
        #pragma unroll
        for (int mt = 0; mt < 2; mt++)
            ldsm_x4(ah[mt], sb + G2_A + aOff + (uint32_t)(mt * 16 * 144 + ks * 32));
        #pragma unroll
        for (int nt2 = 0; nt2 < 4; nt2++) {
            uint32_t bd = sb + G2_BH + bOff + (uint32_t)(ks * 16 * 272 + nt2 * 32);
            ldsm_x4_t(bh[nt2], bd);
            ldsm_x4_t(bl[nt2], bd + (G2_BL - G2_BH));
        }
        #pragma unroll
        for (int mt = 0; mt < 2; mt++) {
            #pragma unroll
            for (int nt = 0; nt < 8; nt++) {
                const uint32_t* ph = &bh[nt >> 1][(nt & 1) * 2];
                const uint32_t* pl = &bl[nt >> 1][(nt & 1) * 2];
                mma_f16(acc[mt][nt], ah[mt], ph);
                mma_f16(acc[mt][nt], ah[mt], pl);
            }
        }
    }

    #pragma unroll
    for (int mt = 0; mt < 2; mt++) {
        int r0 = row0 + wr * 32 + mt * 16 + (lane >> 2);
        #pragma unroll
        for (int nt = 0; nt < 8; nt++) {
            int col = col0 + wc * 64 + nt * 8 + (lane & 3) * 2;
            if (r0 < n)
                *(__half2*)&g_h3h[(size_t)r0 * C_IN + col] =
                    __floats2half2_rn(acc[mt][nt][0], acc[mt][nt][1]);
            if (r0 + 8 < n)
                *(__half2*)&g_h3h[(size_t)(r0 + 8) * C_IN + col] =
                    __floats2half2_rn(acc[mt][nt][2], acc[mt][nt][3]);
        }
    }
    epilogue_partials<8>(acc, row0 + wr * 32, n, lane, wid, tid,
                         g_p3s + ((size_t)blockIdx.y * MAXB + blockIdx.x) * 128,
                         g_p3q + ((size_t)blockIdx.y * MAXB + blockIdx.x) * 128);
}

// ---------------- epilogue: out = elu(bn3(h3_fp16) + data) ----------------
__global__ void final_kernel(const float* __restrict__ data,
                             float* __restrict__ out, long long total) {
    long long i = ((long long)blockIdx.x * blockDim.x + threadIdx.x) * 4;
    if (i >= total) return;
    uint2 hp = *(const uint2*)((const unsigned short*)g_h3h + i);
    float2 f0 = __half22float2(*(__half2*)&hp.x);
    float2 f1 = __half22float2(*(__half2*)&hp.y);
    float4 d = *(const float4*)&data[i];
    int c = (int)(i & (C_IN - 1));
    float4 h;
    float x;
    x = fmaf(g_a3[c],     f0.x, g_c3[c])     + d.x; h.x = x > 0.f ? x : expm1f(x);
    x = fmaf(g_a3[c + 1], f0.y, g_c3[c + 1]) + d.y; h.y = x > 0.f ? x : expm1f(x);
    x = fmaf(g_a3[c + 2], f1.x, g_c3[c + 2]) + d.z; h.z = x > 0.f ? x : expm1f(x);
    x = fmaf(g_a3[c + 3], f1.y, g_c3[c + 3]) + d.w; h.w = x > 0.f ? x : expm1f(x);
    *(float4*)&out[i] = h;
}

// ---------------- launch ----------------
extern "C" void kernel_launch(void* const* d_in, const int* in_sizes, int n_in,
                              void* d_out, int out_size) {
    const float* data  = (const float*)d_in[0];
    const int*   neigh = (const int*)d_in[1];
    const float* w1 = (const float*)d_in[2];
    const float* g1 = (const float*)d_in[3];
    const float* b1 = (const float*)d_in[4];
    const float* w3 = (const float*)d_in[5];
    const float* g3 = (const float*)d_in[6];
    const float* b3 = (const float*)d_in[7];
    const float* w2 = (const float*)d_in[8];
    const float* g2 = (const float*)d_in[9];
    const float* b2 = (const float*)d_in[10];
    float* out = (float*)d_out;

    const int n = in_sizes[0] / C_IN;
    const float inv_n = 1.0f / (float)n;
    const int nblk128 = (n + 127) / 128;
    const long long tot_b = (long long)n * C_B;
    const long long tot_c = (long long)n * C_IN;

    float *a1p, *c1p, *a2p, *c2p, *a3p, *c3p;
    cudaGetSymbolAddress((void**)&a1p, g_a1); cudaGetSymbolAddress((void**)&c1p, g_c1);
    cudaGetSymbolAddress((void**)&a2p, g_a2); cudaGetSymbolAddress((void**)&c2p, g_c2);
    cudaGetSymbolAddress((void**)&a3p, g_a3); cudaGetSymbolAddress((void**)&c3p, g_c3);
    float *p1s, *p1q, *p2s, *p2q, *p3s, *p3q;
    cudaGetSymbolAddress((void**)&p1s, g_p1s); cudaGetSymbolAddress((void**)&p1q, g_p1q);
    cudaGetSymbolAddress((void**)&p2s, g_p2s); cudaGetSymbolAddress((void**)&p2q, g_p2q);
    cudaGetSymbolAddress((void**)&p3s, g_p3s); cudaGetSymbolAddress((void**)&p3q, g_p3q);

    cudaFuncSetAttribute(gemm1_mma_kernel,
                         cudaFuncAttributeMaxDynamicSharedMemorySize, G1_SMEM);
    cudaFuncSetAttribute(octconv_mma_kernel,
                         cudaFuncAttributeMaxDynamicSharedMemorySize, OCT_SMEM);
    cudaFuncSetAttribute(gemm2_mma_kernel,
                         cudaFuncAttributeMaxDynamicSharedMemorySize, G2_SMEM);

    w3_split_kernel<<<(K_TAP * C_B * C_B + 255) / 256, 256>>>(w3);

    gemm1_mma_kernel<<<nblk128, 256, G1_SMEM>>>(data, w1, n);
    reduce_bnfin64<<<64, 256>>>(p1s, p1q, nblk128, g1, b1, a1p, c1p, inv_n);
    act1_kernel<<<(int)((tot_b / 4 + 255) / 256), 256>>>(tot_b);

    octconv_mma_kernel<<<nblk128, 256, OCT_SMEM>>>(neigh, n);
    reduce_bnfin64<<<64, 256>>>(p2s, p2q, nblk128, g3, b3, a2p, c2p, inv_n);

    gemm2_mma_kernel<<<dim3(nblk128, 2), 256, G2_SMEM>>>(w2, n);
    reduce_bnfin256<<<256, 256>>>(p3s, p3q, nblk128, g2, b2, a3p, c3p, inv_n);

    final_kernel<<<(int)((tot_c / 4 + 255) / 256), 256>>>(data, out, tot_c);
}

// round 14
// speedup vs baseline: 2.0198x; 1.2256x over previous
#include <cuda_runtime.h>
#include <cuda_fp16.h>
#include <math.h>
#include <stdint.h>

#define C_IN   256
#define C_B    64
#define K_TAP  27
#define N_MAX  200000
#define MAXB   1600
#define BN_EPS 1e-3f

// ---------------- scratch (device globals; no allocation) ----------------
__device__ float g_h1[(size_t)N_MAX * C_B];   // conv1x1a raw
__device__ float g_h2[(size_t)N_MAX * C_B];   // octree conv raw
__device__ __half g_h3h[(size_t)N_MAX * C_IN]; // conv1x1b raw (fp16)

__device__ __half g_h1h[(size_t)N_MAX * C_B];  // act1 (fp16 rounded)
__device__ __half g_w3h[K_TAP * C_B * C_B];    // w3 [k][c][d] (fp16 rounded)

__device__ float g_a1[C_B],  g_c1[C_B];
__device__ float g_a2[C_B],  g_c2[C_B];
__device__ float g_a3[C_IN], g_c3[C_IN];

// per-block stats partials (no atomics)
__device__ float g_p1s[MAXB * 64],  g_p1q[MAXB * 64];
__device__ float g_p2s[MAXB * 64],  g_p2q[MAXB * 64];
__device__ float g_p3s[2 * MAXB * 128], g_p3q[2 * MAXB * 128];

__device__ __forceinline__ float gelu_exact(float x) {
    return 0.5f * x * (1.0f + erff(x * 0.70710678118654752440f));
}

// ---------------- mma/ldsm/cp.async helpers ----------------
__device__ __forceinline__ uint32_t smem_u32(const void* p) {
    uint32_t a;
    asm("{ .reg .u64 t; cvta.to.shared.u64 t, %1; cvt.u32.u64 %0, t; }"
        : "=r"(a) : "l"(p));
    return a;
}
__device__ __forceinline__ void ldsm_x4(uint32_t* r, uint32_t addr) {
    asm volatile("ldmatrix.sync.aligned.m8n8.x4.shared.b16 {%0,%1,%2,%3}, [%4];"
                 : "=r"(r[0]), "=r"(r[1]), "=r"(r[2]), "=r"(r[3]) : "r"(addr));
}
__device__ __forceinline__ void ldsm_x4_t(uint32_t* r, uint32_t addr) {
    asm volatile("ldmatrix.sync.aligned.m8n8.x4.trans.shared.b16 {%0,%1,%2,%3}, [%4];"
                 : "=r"(r[0]), "=r"(r[1]), "=r"(r[2]), "=r"(r[3]) : "r"(addr));
}
__device__ __forceinline__ void mma_f16(float* d, const uint32_t* a, const uint32_t* b) {
    asm volatile(
        "mma.sync.aligned.m16n8k16.row.col.f32.f16.f16.f32 "
        "{%0,%1,%2,%3}, {%4,%5,%6,%7}, {%8,%9}, {%0,%1,%2,%3};"
        : "+f"(d[0]), "+f"(d[1]), "+f"(d[2]), "+f"(d[3])
        : "r"(a[0]), "r"(a[1]), "r"(a[2]), "r"(a[3]), "r"(b[0]), "r"(b[1]));
}
__device__ __forceinline__ void cp16(uint32_t dst, const void* src) {
    asm volatile("cp.async.cg.shared.global [%0], [%1], 16;" :: "r"(dst), "l"(src));
}
__device__ __forceinline__ void cp_commit() {
    asm volatile("cp.async.commit_group;" ::: "memory");
}

__device__ __forceinline__ uint32_t hpack(__half a, __half b) {
    unsigned short ua = *(unsigned short*)&a, ub = *(unsigned short*)&b;
    return (uint32_t)ua | ((uint32_t)ub << 16);
}
__device__ __forceinline__ uint2 round4h(float4 v) {
    uint2 r;
    r.x = hpack(__float2half_rn(v.x), __float2half_rn(v.y));
    r.y = hpack(__float2half_rn(v.z), __float2half_rn(v.w));
    return r;
}
__device__ __forceinline__ void split4h(float4 v, uint2* hi, uint2* lo) {
    __half h0 = __float2half_rn(v.x), h1 = __float2half_rn(v.y);
    __half h2 = __float2half_rn(v.z), h3 = __float2half_rn(v.w);
    __half l0 = __float2half_rn(v.x - __half2float(h0));
    __half l1 = __float2half_rn(v.y - __half2float(h1));
    __half l2 = __float2half_rn(v.z - __half2float(h2));
    __half l3 = __float2half_rn(v.w - __half2float(h3));
    hi->x = hpack(h0, h1); hi->y = hpack(h2, h3);
    lo->x = hpack(l0, l1); lo->y = hpack(l2, l3);
}

// ---------------- epilogue partial-stats (no atomics) ----------------
template<int NT>
__device__ __forceinline__ void epilogue_partials(const float acc[][NT][4],
                                                  int row0_w, int n,
                                                  int lane, int wid, int tid,
                                                  float* __restrict__ gS,
                                                  float* __restrict__ gQ) {
    __shared__ float sS[8][64], sQ[8][64];
    float cs[NT * 2], cq[NT * 2];
    #pragma unroll
    for (int i = 0; i < NT * 2; i++) { cs[i] = 0.f; cq[i] = 0.f; }
    #pragma unroll
    for (int mt = 0; mt < 2; mt++) {
        int r0 = row0_w + mt * 16 + (lane >> 2);
        bool v0 = r0 < n, v1 = (r0 + 8) < n;
        #pragma unroll
        for (int nt = 0; nt < NT; nt++) {
            #pragma unroll
            for (int j = 0; j < 2; j++) {
                float a0 = acc[mt][nt][j], a1 = acc[mt][nt][2 + j];
                if (v0) { cs[nt * 2 + j] += a0; cq[nt * 2 + j] += a0 * a0; }
                if (v1) { cs[nt * 2 + j] += a1; cq[nt * 2 + j] += a1 * a1; }
            }
        }
    }
    #pragma unroll
    for (int m = 4; m <= 16; m <<= 1) {
        #pragma unroll
        for (int i = 0; i < NT * 2; i++) {
            cs[i] += __shfl_xor_sync(0xffffffffu, cs[i], m);
            cq[i] += __shfl_xor_sync(0xffffffffu, cq[i], m);
        }
    }
    __syncthreads();
    if (lane < 4) {
        #pragma unroll
        for (int i = 0; i < NT * 2; i++) {
            int colw = (i >> 1) * 8 + lane * 2 + (i & 1);
            sS[wid][colw] = cs[i];
            sQ[wid][colw] = cq[i];
        }
    }
    __syncthreads();
    if (tid < NT * 16) {
        int grp = tid / (NT * 8);
        int colw = tid % (NT * 8);
        float s = 0.f, q = 0.f;
        #pragma unroll
        for (int w = 0; w < 4; w++) {
            s += sS[grp * 4 + w][colw];
            q += sQ[grp * 4 + w][colw];
        }
        gS[tid] = s;
        gQ[tid] = q;
    }
}

// ---------------- reduce partials + BN finalize ----------------
__global__ void reduce_bnfin64(const float* __restrict__ pS, const float* __restrict__ pQ,
                               int nblk, const float* __restrict__ g,
                               const float* __restrict__ b,
                               float* __restrict__ a, float* __restrict__ c,
                               float inv_n) {
    __shared__ float sm[256], qm[256];
    int col = blockIdx.x, tid = threadIdx.x;
    float s = 0.f, q = 0.f;
    for (int bx = tid; bx < nblk; bx += 256) {
        s += pS[bx * 64 + col];
        q += pQ[bx * 64 + col];
    }
    sm[tid] = s; qm[tid] = q;
    __syncthreads();
    for (int off = 128; off; off >>= 1) {
        if (tid < off) { sm[tid] += sm[tid + off]; qm[tid] += qm[tid + off]; }
        __syncthreads();
    }
    if (tid == 0) {
        float m = sm[0] * inv_n;
        float v = qm[0] * inv_n - m * m;
        if (v < 0.f) v = 0.f;
        float sc = g[col] * rsqrtf(v + BN_EPS);
        a[col] = sc;
        c[col] = b[col] - m * sc;
    }
}
__global__ void reduce_bnfin256(const float* __restrict__ pS, const float* __restrict__ pQ,
                                int nblk, const float* __restrict__ g,
                                const float* __restrict__ b,
                                float* __restrict__ a, float* __restrict__ c,
                                float inv_n) {
    __shared__ float sm[256], qm[256];
    int col = blockIdx.x, tid = threadIdx.x;
    int by = col >> 7, colw = col & 127;
    const float* ps = pS + (size_t)by * MAXB * 128 + colw;
    const float* pq = pQ + (size_t)by * MAXB * 128 + colw;
    float s = 0.f, q = 0.f;
    for (int bx = tid; bx < nblk; bx += 256) {
        s += ps[bx * 128];
        q += pq[bx * 128];
    }
    sm[tid] = s; qm[tid] = q;
    __syncthreads();
    for (int off = 128; off; off >>= 1) {
        if (tid < off) { sm[tid] += sm[tid + off]; qm[tid] += qm[tid + off]; }
        __syncthreads();
    }
    if (tid == 0) {
        float m = sm[0] * inv_n;
        float v = qm[0] * inv_n - m * m;
        if (v < 0.f) v = 0.f;
        float sc = g[col] * rsqrtf(v + BN_EPS);
        a[col] = sc;
        c[col] = b[col] - m * sc;
    }
}

// ---------------- act1: BN+GELU, write fp16 ----------------
__global__ void act1_kernel(long long total) {
    long long i = ((long long)blockIdx.x * blockDim.x + threadIdx.x) * 4;
    if (i >= total) return;
    float4 v = *(const float4*)&g_h1[i];
    int c = (int)(i & (C_B - 1));
    v.x = gelu_exact(fmaf(g_a1[c],     v.x, g_c1[c]));
    v.y = gelu_exact(fmaf(g_a1[c + 1], v.y, g_c1[c + 1]));
    v.z = gelu_exact(fmaf(g_a1[c + 2], v.z, g_c1[c + 2]));
    v.w = gelu_exact(fmaf(g_a1[c + 3], v.w, g_c1[c + 3]));
    *(uint2*)((unsigned short*)g_h1h + i) = round4h(v);
}

// ---------------- w3 round to fp16 (keep [k][c][d] layout) ----------------
__global__ void w3_split_kernel(const float* __restrict__ w3) {
    int i = blockIdx.x * blockDim.x + threadIdx.x;
    if (i >= K_TAP * C_B * C_B) return;
    g_w3h[i] = __float2half_rn(w3[i]);
}

// ============== GEMM1 via mma.sync fp16: h1 = data[N,256] @ w1[256,64] ==============
#define G1_A  0
#define G1_BH 18432
#define G1_BL 27648
#define G1_SMEM 36864

__global__ void __launch_bounds__(256) gemm1_mma_kernel(const float* __restrict__ data,
                                                        const float* __restrict__ w1, int n) {
    extern __shared__ char smem[];
    const uint32_t sb = smem_u32(smem);
    const int tid = threadIdx.x;
    const int wid = tid >> 5, lane = tid & 31;
    const int wr = wid & 3, wc = wid >> 2;
    const int row0 = blockIdx.x * 128;

    float acc[2][4][4] = {};
    const uint32_t aOff = (uint32_t)((wr * 32 + (lane & 15)) * 144 + (lane >> 4) * 16);
    const uint32_t bOff = (uint32_t)((lane & 15) * 144 + (wc * 32 + (lane >> 4) * 8) * 2);

    for (int kb = 0; kb < C_IN; kb += 64) {
        #pragma unroll
        for (int j = 0; j < 8; j++) {
            int s = tid + 256 * j;
            int r = s >> 4, f4 = s & 15;
            int rr = row0 + r; if (rr >= n) rr = n - 1;
            float4 v = *(const float4*)(data + (size_t)rr * C_IN + kb + f4 * 4);
            *(uint2*)(smem + G1_A + r * 144 + f4 * 8) = round4h(v);
        }
        #pragma unroll
        for (int j = 0; j < 4; j++) {
            int s = tid + 256 * j;
            int r = s >> 4, f4 = s & 15;
            float4 v = *(const float4*)(w1 + (size_t)(kb + r) * C_B + f4 * 4);
            uint2 hi, lo; split4h(v, &hi, &lo);
            *(uint2*)(smem + G1_BH + r * 144 + f4 * 8) = hi;
            *(uint2*)(smem + G1_BL + r * 144 + f4 * 8) = lo;
        }
        __syncthreads();

        #pragma unroll
        for (int ks = 0; ks < 4; ks++) {
            uint32_t ah[2][4], bh[2][4], bl[2][4];
            #pragma unroll
            for (int mt = 0; mt < 2; mt++)
                ldsm_x4(ah[mt], sb + G1_A + aOff + (uint32_t)(mt * 16 * 144 + ks * 32));
            #pragma unroll
            for (int nt2 = 0; nt2 < 2; nt2++) {
                uint32_t bd = sb + G1_BH + bOff + (uint32_t)(ks * 16 * 144 + nt2 * 32);
                ldsm_x4_t(bh[nt2], bd);
                ldsm_x4_t(bl[nt2], bd + (G1_BL - G1_BH));
            }
            #pragma unroll
            for (int mt = 0; mt < 2; mt++) {
                #pragma unroll
                for (int nt = 0; nt < 4; nt++) {
                    const uint32_t* ph = &bh[nt >> 1][(nt & 1) * 2];
                    const uint32_t* pl = &bl[nt >> 1][(nt & 1) * 2];
                    mma_f16(acc[mt][nt], ah[mt], ph);
                    mma_f16(acc[mt][nt], ah[mt], pl);
                }
            }
        }
        __syncthreads();
    }

    #pragma unroll
    for (int mt = 0; mt < 2; mt++) {
        int r0 = row0 + wr * 32 + mt * 16 + (lane >> 2);
        #pragma unroll
        for (int nt = 0; nt < 4; nt++) {
            int col = wc * 32 + nt * 8 + (lane & 3) * 2;
            if (r0 < n)
                *(float2*)&g_h1[(size_t)r0 * C_B + col] =
                    make_float2(acc[mt][nt][0], acc[mt][nt][1]);
            if (r0 + 8 < n)
                *(float2*)&g_h1[(size_t)(r0 + 8) * C_B + col] =
                    make_float2(acc[mt][nt][2], acc[mt][nt][3]);
        }
    }
    epilogue_partials<4>(acc, row0 + wr * 32, n, lane, wid, tid,
                         g_p1s + (size_t)blockIdx.x * 64,
                         g_p1q + (size_t)blockIdx.x * 64);
}

// ============== octree conv via mma.sync fp16 (1-term) + cp.async double buffering ==============
#define OB_A  0
#define OB_WH 18432
#define OB_SZ 27648
#define OFF_IDX 0
#define OFF_BUF 13824
#define OCT_SMEM (OFF_BUF + 2 * OB_SZ)   // 69120

__device__ __forceinline__ void issue_tap(uint32_t sb, int buf, int k,
                                          const int* sIdx, int tid) {
    const uint32_t base = sb + OFF_BUF + buf * OB_SZ;
    const int* idx = sIdx + (k << 7);
    #pragma unroll
    for (int j = 0; j < 4; j++) {
        int cid = tid + 256 * j;              // 0..1023
        int r = cid >> 3, q = cid & 7;
        int gr = idx[r];
        cp16(base + OB_A + (uint32_t)(r * 144 + q * 16),
             g_h1h + (size_t)gr * C_B + q * 8);
    }
    #pragma unroll
    for (int j = 0; j < 2; j++) {
        int cid = tid + 256 * j;              // 0..511
        int r = cid >> 3, q = cid & 7;
        cp16(base + OB_WH + (uint32_t)(r * 144 + q * 16),
             g_w3h + (size_t)k * 4096 + cid * 8);
    }
}

__global__ void __launch_bounds__(256) octconv_mma_kernel(const int* __restrict__ neigh,
                                                          int n) {
    extern __shared__ char smem[];
    const uint32_t sb = smem_u32(smem);
    const int tid = threadIdx.x;
    const int wid = tid >> 5, lane = tid & 31;
    const int wr = wid & 3, wc = wid >> 2;
    const int row0 = blockIdx.x * 128;

    int* sIdx = (int*)(smem + OFF_IDX);
    for (int i = tid; i < K_TAP * 128; i += 256) {
        int r = i / K_TAP, k = i - r * K_TAP;
        int nr = row0 + r;
        sIdx[k * 128 + r] = (nr < n) ? neigh[(size_t)nr * K_TAP + k] : 0;
    }
    __syncthreads();

    issue_tap(sb, 0, 0, sIdx, tid);
    cp_commit();

    float acc[2][4][4] = {};
    const uint32_t aOff = (uint32_t)((wr * 32 + (lane & 15)) * 144 + (lane >> 4) * 16);
    const uint32_t bOff = (uint32_t)((lane & 15) * 144 + (wc * 32 + (lane >> 4) * 8) * 2);

    for (int k = 0; k < K_TAP; k++) {
        const int b = k & 1;
        if (k + 1 < K_TAP) {
            issue_tap(sb, b ^ 1, k + 1, sIdx, tid);
            cp_commit();
            asm volatile("cp.async.wait_group 1;" ::: "memory");
        } else {
            asm volatile("cp.async.wait_group 0;" ::: "memory");
        }
        __syncthreads();

        const uint32_t base = sb + OFF_BUF + b * OB_SZ;
        #pragma unroll
        for (int ks = 0; ks < 4; ks++) {
            uint32_t ah[2][4], bh[2][4];
            #pragma unroll
            for (int mt = 0; mt < 2; mt++)
                ldsm_x4(ah[mt], base + OB_A + aOff + (uint32_t)(mt * 16 * 144 + ks * 32));
            #pragma unroll
            for (int nt2 = 0; nt2 < 2; nt2++)
                ldsm_x4_t(bh[nt2], base + OB_WH + bOff + (uint32_t)(ks * 16 * 144 + nt2 * 32));
            #pragma unroll
            for (int mt = 0; mt < 2; mt++) {
                #pragma unroll
                for (int nt = 0; nt < 4; nt++) {
                    const uint32_t* ph = &bh[nt >> 1][(nt & 1) * 2];
                    mma_f16(acc[mt][nt], ah[mt], ph);
                }
            }
        }
        __syncthreads();
    }

    #pragma unroll
    for (int mt = 0; mt < 2; mt++) {
        int r0 = row0 + wr * 32 + mt * 16 + (lane >> 2);
        #pragma unroll
        for (int nt = 0; nt < 4; nt++) {
            int col = wc * 32 + nt * 8 + (lane & 3) * 2;
            if (r0 < n)
                *(float2*)&g_h2[(size_t)r0 * C_B + col] =
                    make_float2(acc[mt][nt][0], acc[mt][nt][1]);
            if (r0 + 8 < n)
                *(float2*)&g_h2[(size_t)(r0 + 8) * C_B + col] =
                    make_float2(acc[mt][nt][2], acc[mt][nt][3]);
        }
    }
    epilogue_partials<4>(acc, row0 + wr * 32, n, lane, wid, tid,
                         g_p2s + (size_t)blockIdx.x * 64,
                         g_p2q + (size_t)blockIdx.x * 64);
}

// ============== GEMM2 via mma.sync fp16: h3 = act2(h2)[N,64] @ w2[64,256] ==============
#define G2_A  0
#define G2_BH 18432
#define G2_BL (18432 + 17408)
#define G2_SMEM (18432 + 2 * 17408)   // 53248

__global__ void __launch_bounds__(256) gemm2_mma_kernel(const float* __restrict__ w2, int n) {
    extern __shared__ char smem[];
    const uint32_t sb = smem_u32(smem);
    const int tid = threadIdx.x;
    const int wid = tid >> 5, lane = tid & 31;
    const int wr = wid & 3, wc = wid >> 2;
    const int row0 = blockIdx.x * 128;
    const int col0 = blockIdx.y * 128;

    #pragma unroll
    for (int j = 0; j < 8; j++) {
        int s = tid + 256 * j;
        int r = s >> 4, f4 = s & 15;
        int rr = row0 + r; if (rr >= n) rr = n - 1;
        float4 v = *(const float4*)(g_h2 + (size_t)rr * C_B + f4 * 4);
        int c = f4 * 4;
        v.x = gelu_exact(fmaf(g_a2[c],     v.x, g_c2[c]));
        v.y = gelu_exact(fmaf(g_a2[c + 1], v.y, g_c2[c + 1]));
        v.z = gelu_exact(fmaf(g_a2[c + 2], v.z, g_c2[c + 2]));
        v.w = gelu_exact(fmaf(g_a2[c + 3], v.w, g_c2[c + 3]));
        *(uint2*)(smem + G2_A + r * 144 + f4 * 8) = round4h(v);
    }
    #pragma unroll
    for (int j = 0; j < 8; j++) {
        int s = tid + 256 * j;                // 0..2047
        int r = s >> 5, f4 = s & 31;
        float4 v = *(const float4*)(w2 + (size_t)r * C_IN + col0 + f4 * 4);
        uint2 hi, lo; split4h(v, &hi, &lo);
        *(uint2*)(smem + G2_BH + r * 272 + f4 * 8) = hi;
        *(uint2*)(smem + G2_BL + r * 272 + f4 * 8) = lo;
    }
    __syncthreads();

    float acc[2][8][4] = {};
    const uint32_t aOff = (uint32_t)((wr * 32 + (lane & 15)) * 144 + (lane >> 4) * 16);
    const uint32_t bOff = (uint32_t)((lane & 15) * 272 + (wc * 64 + (lane >> 4) * 8) * 2);

    #pragma unroll
    for (int ks = 0; ks < 4; ks++) {
        uint32_t ah[2][4], bh[4][4], bl[4][4];
        #pragma unroll
        for (int mt = 0; mt < 2; mt++)
            ldsm_x4(ah[mt], sb + G2_A + aOff + (uint32_t)(mt * 16 * 144 + ks * 32));
        #pragma unroll
        for (int nt2 = 0; nt2 < 4; nt2++) {
            uint32_t bd = sb + G2_BH + bOff + (uint32_t)(ks * 16 * 272 + nt2 * 32);
            ldsm_x4_t(bh[nt2], bd);
            ldsm_x4_t(bl[nt2], bd + (G2_BL - G2_BH));
        }
        #pragma unroll
        for (int mt = 0; mt < 2; mt++) {
            #pragma unroll
            for (int nt = 0; nt < 8; nt++) {
                const uint32_t* ph = &bh[nt >> 1][(nt & 1) * 2];
                const uint32_t* pl = &bl[nt >> 1][(nt & 1) * 2];
                mma_f16(acc[mt][nt], ah[mt], ph);
                mma_f16(acc[mt][nt], ah[mt], pl);
            }
        }
    }

    #pragma unroll
    for (int mt = 0; mt < 2; mt++) {
        int r0 = row0 + wr * 32 + mt * 16 + (lane >> 2);
        #pragma unroll
        for (int nt = 0; nt < 8; nt++) {
            int col = col0 + wc * 64 + nt * 8 + (lane & 3) * 2;
            if (r0 < n)
                *(__half2*)&g_h3h[(size_t)r0 * C_IN + col] =
                    __floats2half2_rn(acc[mt][nt][0], acc[mt][nt][1]);
            if (r0 + 8 < n)
                *(__half2*)&g_h3h[(size_t)(r0 + 8) * C_IN + col] =
                    __floats2half2_rn(acc[mt][nt][2], acc[mt][nt][3]);
        }
    }
    epilogue_partials<8>(acc, row0 + wr * 32, n, lane, wid, tid,
                         g_p3s + ((size_t)blockIdx.y * MAXB + blockIdx.x) * 128,
                         g_p3q + ((size_t)blockIdx.y * MAXB + blockIdx.x) * 128);
}

// ---------------- epilogue: out = elu(bn3(h3_fp16) + data) ----------------
__global__ void final_kernel(const float* __restrict__ data,
                             float* __restrict__ out, long long total) {
    long long i = ((long long)blockIdx.x * blockDim.x + threadIdx.x) * 4;
    if (i >= total) return;
    uint2 hp = *(const uint2*)((const unsigned short*)g_h3h + i);
    float2 f0 = __half22float2(*(__half2*)&hp.x);
    float2 f1 = __half22float2(*(__half2*)&hp.y);
    float4 d = *(const float4*)&data[i];
    int c = (int)(i & (C_IN - 1));
    float4 h;
    float x;
    x = fmaf(g_a3[c],     f0.x, g_c3[c])     + d.x; h.x = x > 0.f ? x : expm1f(x);
    x = fmaf(g_a3[c + 1], f0.y, g_c3[c + 1]) + d.y; h.y = x > 0.f ? x : expm1f(x);
    x = fmaf(g_a3[c + 2], f1.x, g_c3[c + 2]) + d.z; h.z = x > 0.f ? x : expm1f(x);
    x = fmaf(g_a3[c + 3], f1.y, g_c3[c + 3]) + d.w; h.w = x > 0.f ? x : expm1f(x);
    *(float4*)&out[i] = h;
}

// ---------------- launch ----------------
extern "C" void kernel_launch(void* const* d_in, const int* in_sizes, int n_in,
                              void* d_out, int out_size) {
    const float* data  = (const float*)d_in[0];
    const int*   neigh = (const int*)d_in[1];
    const float* w1 = (const float*)d_in[2];
    const float* g1 = (const float*)d_in[3];
    const float* b1 = (const float*)d_in[4];
    const float* w3 = (const float*)d_in[5];
    const float* g3 = (const float*)d_in[6];
    const float* b3 = (const float*)d_in[7];
    const float* w2 = (const float*)d_in[8];
    const float* g2 = (const float*)d_in[9];
    const float* b2 = (const float*)d_in[10];
    float* out = (float*)d_out;

    const int n = in_sizes[0] / C_IN;
    const float inv_n = 1.0f / (float)n;
    const int nblk128 = (n + 127) / 128;
    const long long tot_b = (long long)n * C_B;
    const long long tot_c = (long long)n * C_IN;

    float *a1p, *c1p, *a2p, *c2p, *a3p, *c3p;
    cudaGetSymbolAddress((void**)&a1p, g_a1); cudaGetSymbolAddress((void**)&c1p, g_c1);
    cudaGetSymbolAddress((void**)&a2p, g_a2); cudaGetSymbolAddress((void**)&c2p, g_c2);
    cudaGetSymbolAddress((void**)&a3p, g_a3); cudaGetSymbolAddress((void**)&c3p, g_c3);
    float *p1s, *p1q, *p2s, *p2q, *p3s, *p3q;
    cudaGetSymbolAddress((void**)&p1s, g_p1s); cudaGetSymbolAddress((void**)&p1q, g_p1q);
    cudaGetSymbolAddress((void**)&p2s, g_p2s); cudaGetSymbolAddress((void**)&p2q, g_p2q);
    cudaGetSymbolAddress((void**)&p3s, g_p3s); cudaGetSymbolAddress((void**)&p3q, g_p3q);

    cudaFuncSetAttribute(gemm1_mma_kernel,
                         cudaFuncAttributeMaxDynamicSharedMemorySize, G1_SMEM);
    cudaFuncSetAttribute(octconv_mma_kernel,
                         cudaFuncAttributeMaxDynamicSharedMemorySize, OCT_SMEM);
    cudaFuncSetAttribute(gemm2_mma_kernel,
                         cudaFuncAttributeMaxDynamicSharedMemorySize, G2_SMEM);

    w3_split_kernel<<<(K_TAP * C_B * C_B + 255) / 256, 256>>>(w3);

    gemm1_mma_kernel<<<nblk128, 256, G1_SMEM>>>(data, w1, n);
    reduce_bnfin64<<<64, 256>>>(p1s, p1q, nblk128, g1, b1, a1p, c1p, inv_n);
    act1_kernel<<<(int)((tot_b / 4 + 255) / 256), 256>>>(tot_b);

    octconv_mma_kernel<<<nblk128, 256, OCT_SMEM>>>(neigh, n);
    reduce_bnfin64<<<64, 256>>>(p2s, p2q, nblk128, g3, b3, a2p, c2p, inv_n);

    gemm2_mma_kernel<<<dim3(nblk128, 2), 256, G2_SMEM>>>(w2, n);
    reduce_bnfin256<<<256, 256>>>(p3s, p3q, nblk128, g2, b2, a3p, c3p, inv_n);

    final_kernel<<<(int)((tot_c / 4 + 255) / 256), 256>>>(data, out, tot_c);
}